// round 1
// baseline (speedup 1.0000x reference)
#include <cuda_runtime.h>

#define S_LEN 4096
#define DM    768
#define NH    12
#define DK    64

// Scratch (device globals — no allocation allowed in kernel_launch)
__device__ float g_Q[DM * S_LEN];    // [h*64+d][s]  (transposed per head)
__device__ float g_K[DM * S_LEN];    // [h*64+d][s]
__device__ float g_V[S_LEN * DM];    // [s][h*64+d]  (natural)
__device__ float g_ctx[S_LEN * DM];  // attention output, natural

// ---------------------------------------------------------------------------
// GEMM: C = A[M,K] @ B[N,K]^T  (both K-contiguous).
// TOUT=false: C natural [M,N].  TOUT=true: C transposed [N,M].
// 128x128 block tile, BK=8, 256 threads, 8x8 microtile, double-buffered smem.
// ---------------------------------------------------------------------------
template<bool TOUT>
__global__ __launch_bounds__(256)
void gemm_nt(const float* __restrict__ A, const float* __restrict__ B,
             float* __restrict__ C, int M, int N, int K)
{
    const int BM = 128, BN = 128, BK = 8;
    __shared__ float As[2][BK][BM + 4];
    __shared__ float Bs[2][BK][BN + 4];

    const int tid = threadIdx.x;
    const int tx = tid & 15;        // 0..15 -> N microtile
    const int ty = tid >> 4;        // 0..15 -> M microtile
    const int bm = blockIdx.x * BM;
    const int bn = blockIdx.y * BN;

    // global load mapping: each thread loads one float4 of A and one of B per step
    const int lm = tid >> 1;          // 0..127 (row within tile)
    const int lk = (tid & 1) * 4;     // 0 or 4 (k offset)
    const float* Aptr = A + (size_t)(bm + lm) * K + lk;
    const float* Bptr = B + (size_t)(bn + lm) * K + lk;

    float acc[8][8];
    #pragma unroll
    for (int i = 0; i < 8; i++)
        #pragma unroll
        for (int j = 0; j < 8; j++) acc[i][j] = 0.0f;

    const int nk = K / BK;
    float4 a_n = *(const float4*)(Aptr);
    float4 b_n = *(const float4*)(Bptr);

    int buf = 0;
    for (int s = 0; s < nk; ++s) {
        As[buf][lk + 0][lm] = a_n.x;
        As[buf][lk + 1][lm] = a_n.y;
        As[buf][lk + 2][lm] = a_n.z;
        As[buf][lk + 3][lm] = a_n.w;
        Bs[buf][lk + 0][lm] = b_n.x;
        Bs[buf][lk + 1][lm] = b_n.y;
        Bs[buf][lk + 2][lm] = b_n.z;
        Bs[buf][lk + 3][lm] = b_n.w;
        __syncthreads();

        if (s + 1 < nk) {
            a_n = *(const float4*)(Aptr + (size_t)(s + 1) * BK);
            b_n = *(const float4*)(Bptr + (size_t)(s + 1) * BK);
        }

        #pragma unroll
        for (int k = 0; k < BK; k++) {
            float4 a0 = *(const float4*)&As[buf][k][ty * 8];
            float4 a1 = *(const float4*)&As[buf][k][ty * 8 + 4];
            float4 b0 = *(const float4*)&Bs[buf][k][tx * 8];
            float4 b1 = *(const float4*)&Bs[buf][k][tx * 8 + 4];
            float av[8] = {a0.x, a0.y, a0.z, a0.w, a1.x, a1.y, a1.z, a1.w};
            float bv[8] = {b0.x, b0.y, b0.z, b0.w, b1.x, b1.y, b1.z, b1.w};
            #pragma unroll
            for (int i = 0; i < 8; i++)
                #pragma unroll
                for (int j = 0; j < 8; j++)
                    acc[i][j] = fmaf(av[i], bv[j], acc[i][j]);
        }
        buf ^= 1;
    }

    if (!TOUT) {
        #pragma unroll
        for (int i = 0; i < 8; i++) {
            int row = bm + ty * 8 + i;
            float4 v0 = make_float4(acc[i][0], acc[i][1], acc[i][2], acc[i][3]);
            float4 v1 = make_float4(acc[i][4], acc[i][5], acc[i][6], acc[i][7]);
            *(float4*)&C[(size_t)row * N + bn + tx * 8]     = v0;
            *(float4*)&C[(size_t)row * N + bn + tx * 8 + 4] = v1;
        }
    } else {
        // C^T: element (n, m) at n*M + m. Per-thread column stores are 32B-contiguous.
        #pragma unroll
        for (int j = 0; j < 8; j++) {
            int n = bn + tx * 8 + j;
            float4 v0 = make_float4(acc[0][j], acc[1][j], acc[2][j], acc[3][j]);
            float4 v1 = make_float4(acc[4][j], acc[5][j], acc[6][j], acc[7][j]);
            *(float4*)&C[(size_t)n * M + bm + ty * 8]     = v0;
            *(float4*)&C[(size_t)n * M + bm + ty * 8 + 4] = v1;
        }
    }
}

// ---------------------------------------------------------------------------
// Causal flash attention, fp32. One block = (head, 64-query tile).
// Q/K read from per-head transposed layout [d][s] -> conflict-free smem tiles.
// Online softmax stats kept in registers (replicated across tx group).
// ---------------------------------------------------------------------------
#define QS_OFF 0
#define KS_OFF (64 * 68)
#define SS_OFF (2 * 64 * 68)
#define VS_OFF (3 * 64 * 68)
#define ATTN_SMEM_BYTES ((3 * 64 * 68 + 64 * 64) * 4)

__global__ __launch_bounds__(256)
void attn_kernel()
{
    extern __shared__ float sm[];
    float* Qs = sm + QS_OFF;   // [d][i]  stride 68
    float* Ks = sm + KS_OFF;   // [d][j]  stride 68
    float* Ss = sm + SS_OFF;   // [i][j]  stride 68 (holds P)
    float* Vs = sm + VS_OFF;   // [j][d]  stride 64

    const int tid = threadIdx.x;
    const int tx = tid & 15;   // key/value-d microtile
    const int ty = tid >> 4;   // query microtile
    const int qb = blockIdx.x; // query tile 0..63
    const int h  = blockIdx.y; // head 0..11
    const float scale = 0.125f; // 1/sqrt(64)

    // Load Q tile (once): Qs[d][i] <- g_Q[(h*64+d)*S + qb*64 + i]
    #pragma unroll
    for (int r = 0; r < 4; r++) {
        int idx = tid + r * 256;
        int d = idx >> 4, seg = (idx & 15) * 4;
        float4 v = *(const float4*)&g_Q[(size_t)(h * 64 + d) * S_LEN + qb * 64 + seg];
        *(float4*)&Qs[d * 68 + seg] = v;
    }

    float m_i[4], l_i[4], o[4][4];
    #pragma unroll
    for (int i = 0; i < 4; i++) {
        m_i[i] = -1e30f; l_i[i] = 0.0f;
        #pragma unroll
        for (int d = 0; d < 4; d++) o[i][d] = 0.0f;
    }

    for (int kb = 0; kb <= qb; ++kb) {
        __syncthreads();  // prev PV done / Qs ready; safe to overwrite K,V

        #pragma unroll
        for (int r = 0; r < 4; r++) {
            int idx = tid + r * 256;
            int d = idx >> 4, seg = (idx & 15) * 4;
            float4 kv = *(const float4*)&g_K[(size_t)(h * 64 + d) * S_LEN + kb * 64 + seg];
            *(float4*)&Ks[d * 68 + seg] = kv;
            int j = d; // reuse decomposition: j = idx>>4, dseg = seg
            float4 vv = *(const float4*)&g_V[(size_t)(kb * 64 + j) * DM + h * 64 + seg];
            *(float4*)&Vs[j * 64 + seg] = vv;
        }
        __syncthreads();

        // S = (Q K^T) * scale
        float sacc[4][4];
        #pragma unroll
        for (int i = 0; i < 4; i++)
            #pragma unroll
            for (int j = 0; j < 4; j++) sacc[i][j] = 0.0f;

        #pragma unroll 8
        for (int d = 0; d < 64; d++) {
            float4 a = *(const float4*)&Qs[d * 68 + ty * 4];
            float4 b = *(const float4*)&Ks[d * 68 + tx * 4];
            float av[4] = {a.x, a.y, a.z, a.w};
            float bv[4] = {b.x, b.y, b.z, b.w};
            #pragma unroll
            for (int i = 0; i < 4; i++)
                #pragma unroll
                for (int j = 0; j < 4; j++)
                    sacc[i][j] = fmaf(av[i], bv[j], sacc[i][j]);
        }

        if (kb == qb) {
            #pragma unroll
            for (int i = 0; i < 4; i++) {
                int row = qb * 64 + ty * 4 + i;
                #pragma unroll
                for (int j = 0; j < 4; j++) {
                    int col = kb * 64 + tx * 4 + j;
                    sacc[i][j] = (col > row) ? -1e30f : sacc[i][j] * scale;
                }
            }
        } else {
            #pragma unroll
            for (int i = 0; i < 4; i++)
                #pragma unroll
                for (int j = 0; j < 4; j++) sacc[i][j] *= scale;
        }

        // Online softmax. Row group = 16 lanes sharing ty (lane bits 0..3 = tx).
        #pragma unroll
        for (int i = 0; i < 4; i++) {
            float rm = fmaxf(fmaxf(sacc[i][0], sacc[i][1]), fmaxf(sacc[i][2], sacc[i][3]));
            #pragma unroll
            for (int off = 1; off < 16; off <<= 1)
                rm = fmaxf(rm, __shfl_xor_sync(0xffffffffu, rm, off));
            float m_new = fmaxf(m_i[i], rm);
            float alpha = __expf(m_i[i] - m_new);
            float rs = 0.0f;
            #pragma unroll
            for (int j = 0; j < 4; j++) {
                sacc[i][j] = __expf(sacc[i][j] - m_new);
                rs += sacc[i][j];
            }
            #pragma unroll
            for (int off = 1; off < 16; off <<= 1)
                rs += __shfl_xor_sync(0xffffffffu, rs, off);
            l_i[i] = l_i[i] * alpha + rs;
            m_i[i] = m_new;
            #pragma unroll
            for (int d = 0; d < 4; d++) o[i][d] *= alpha;
            // stage P row segment
            *(float4*)&Ss[(ty * 4 + i) * 68 + tx * 4] =
                make_float4(sacc[i][0], sacc[i][1], sacc[i][2], sacc[i][3]);
        }
        __syncthreads();

        // O += P @ V
        #pragma unroll 4
        for (int j = 0; j < 64; j++) {
            float4 v = *(const float4*)&Vs[j * 64 + tx * 4];
            float vv[4] = {v.x, v.y, v.z, v.w};
            #pragma unroll
            for (int i = 0; i < 4; i++) {
                float p = Ss[(ty * 4 + i) * 68 + j];
                #pragma unroll
                for (int d = 0; d < 4; d++)
                    o[i][d] = fmaf(p, vv[d], o[i][d]);
            }
        }
    }

    // normalize + write ctx (natural layout)
    #pragma unroll
    for (int i = 0; i < 4; i++) {
        float inv = 1.0f / l_i[i];
        float4 v = make_float4(o[i][0] * inv, o[i][1] * inv, o[i][2] * inv, o[i][3] * inv);
        *(float4*)&g_ctx[(size_t)(qb * 64 + ty * 4 + i) * DM + h * 64 + tx * 4] = v;
    }
}

// ---------------------------------------------------------------------------
extern "C" void kernel_launch(void* const* d_in, const int* in_sizes, int n_in,
                              void* d_out, int out_size)
{
    const float* x  = (const float*)d_in[0];
    const float* Wq = (const float*)d_in[1];
    const float* Wk = (const float*)d_in[2];
    const float* Wv = (const float*)d_in[3];
    const float* Wo = (const float*)d_in[4];
    float* out = (float*)d_out;

    float *pQ, *pK, *pV, *pC;
    cudaGetSymbolAddress((void**)&pQ, g_Q);
    cudaGetSymbolAddress((void**)&pK, g_K);
    cudaGetSymbolAddress((void**)&pV, g_V);
    cudaGetSymbolAddress((void**)&pC, g_ctx);

    cudaFuncSetAttribute(attn_kernel,
                         cudaFuncAttributeMaxDynamicSharedMemorySize,
                         ATTN_SMEM_BYTES);

    dim3 gg(S_LEN / 128, DM / 128);  // (32, 6)
    dim3 gb(256);

    gemm_nt<true ><<<gg, gb>>>(x,  Wq, pQ, S_LEN, DM, DM);  // Q^T per head
    gemm_nt<true ><<<gg, gb>>>(x,  Wk, pK, S_LEN, DM, DM);  // K^T per head
    gemm_nt<false><<<gg, gb>>>(x,  Wv, pV, S_LEN, DM, DM);  // V natural

    attn_kernel<<<dim3(S_LEN / 64, NH), 256, ATTN_SMEM_BYTES>>>();

    gemm_nt<false><<<gg, gb>>>(pC, Wo, out, S_LEN, DM, DM); // output proj
}

// round 3
// speedup vs baseline: 1.2612x; 1.2612x over previous
#include <cuda_runtime.h>
#include <cuda_bf16.h>
#include <cstdint>

#define S_LEN 4096
#define DM    768
#define NH    12
#define DK    64

// Scratch (device globals — no allocation allowed in kernel_launch)
__device__ float g_Q[DM * S_LEN];    // [h*64+d][s]  (transposed per head)
__device__ float g_K[DM * S_LEN];    // [h*64+d][s]
__device__ float g_V[S_LEN * DM];    // [s][h*64+d]  (natural)
__device__ float g_ctx[S_LEN * DM];  // attention output, natural

// ===========================================================================
// helpers
// ===========================================================================
__device__ __forceinline__ uint32_t smem_u32(const void* p) {
    uint32_t a;
    asm("{ .reg .u64 t; cvta.to.shared.u64 t, %1; cvt.u32.u64 %0, t; }"
        : "=r"(a) : "l"(p));
    return a;
}

__device__ __forceinline__ void ldsm_x4(uint32_t* r, uint32_t addr) {
    asm volatile("ldmatrix.sync.aligned.m8n8.x4.shared.b16 {%0,%1,%2,%3}, [%4];"
                 : "=r"(r[0]), "=r"(r[1]), "=r"(r[2]), "=r"(r[3]) : "r"(addr));
}

__device__ __forceinline__ void mma_bf16(float* d, const uint32_t* a,
                                         uint32_t b0, uint32_t b1) {
    asm volatile("mma.sync.aligned.m16n8k16.row.col.f32.bf16.bf16.f32 "
                 "{%0,%1,%2,%3}, {%4,%5,%6,%7}, {%8,%9}, {%0,%1,%2,%3};"
                 : "+f"(d[0]), "+f"(d[1]), "+f"(d[2]), "+f"(d[3])
                 : "r"(a[0]), "r"(a[1]), "r"(a[2]), "r"(a[3]), "r"(b0), "r"(b1));
}

__device__ __forceinline__ void sts_v2(uint32_t addr, uint32_t a, uint32_t b) {
    asm volatile("st.shared.v2.b32 [%0], {%1, %2};" :: "r"(addr), "r"(a), "r"(b)
                 : "memory");
}

// split fp32x4 into hi/lo bf16x2 pairs and store (8B each)
__device__ __forceinline__ void split_store(uint32_t hi_addr, uint32_t lo_addr, float4 v) {
    __nv_bfloat16 h0 = __float2bfloat16(v.x);
    __nv_bfloat16 h1 = __float2bfloat16(v.y);
    __nv_bfloat16 h2 = __float2bfloat16(v.z);
    __nv_bfloat16 h3 = __float2bfloat16(v.w);
    float l0 = v.x - __bfloat162float(h0);
    float l1 = v.y - __bfloat162float(h1);
    float l2 = v.z - __bfloat162float(h2);
    float l3 = v.w - __bfloat162float(h3);
    __nv_bfloat162 hp0 = {h0, h1}, hp1 = {h2, h3};
    __nv_bfloat162 lp0 = {__float2bfloat16(l0), __float2bfloat16(l1)};
    __nv_bfloat162 lp1 = {__float2bfloat16(l2), __float2bfloat16(l3)};
    sts_v2(hi_addr, *(uint32_t*)&hp0, *(uint32_t*)&hp1);
    sts_v2(lo_addr, *(uint32_t*)&lp0, *(uint32_t*)&lp1);
}

// ===========================================================================
// bf16x3 tensor-core GEMM: C[M,N] = A[M,K] @ B[N,K]^T  (natural output)
// 128x128 CTA tile, BK=32, 256 threads, warp grid 4(M)x2(N) -> warp tile 32x64.
// smem rows padded to 40 bf16 (80B) -> conflict-free ldmatrix.
// ===========================================================================
#define ROWB      80                      // bytes per padded smem row
#define TILE_B    (128 * ROWB)            // 10240 B
#define AHI_OFF   0
#define ALO_OFF   (1 * TILE_B)
#define BHI_OFF   (2 * TILE_B)
#define BLO_OFF   (3 * TILE_B)
#define BUF_B     (4 * TILE_B)            // 40960
#define GEMM_SMEM (2 * BUF_B)             // 81920

__global__ __launch_bounds__(256)
void gemm_bf16x3(const float* __restrict__ A, const float* __restrict__ B,
                 float* __restrict__ C, int M, int N, int K)
{
    extern __shared__ __align__(128) char dynsm[];
    const uint32_t sbase = smem_u32(dynsm);

    const int tid  = threadIdx.x;
    const int lane = tid & 31;
    const int warp = tid >> 5;
    const int wm = warp >> 1;            // 0..3
    const int wn = warp & 1;             // 0..1
    const int m0 = wm * 32;
    const int n0 = wn * 64;
    const int bm = blockIdx.x * 128;
    const int bn = blockIdx.y * 128;

    // global load mapping: idx = tid + i*256; r = idx>>3 (row), c4 = idx&7
    const int gr  = tid >> 3;            // base row step 32
    const int gc4 = tid & 7;

    float acc[2][8][4];
    #pragma unroll
    for (int mt = 0; mt < 2; mt++)
        #pragma unroll
        for (int nf = 0; nf < 8; nf++)
            #pragma unroll
            for (int e = 0; e < 4; e++) acc[mt][nf][e] = 0.0f;

    const int nchunk = K / 32;           // 24

    float4 pa[4], pb[4];
    #pragma unroll
    for (int i = 0; i < 4; i++) {
        const int r = gr + i * 32;
        pa[i] = *(const float4*)&A[(size_t)(bm + r) * K + gc4 * 4];
        pb[i] = *(const float4*)&B[(size_t)(bn + r) * K + gc4 * 4];
    }

    // ldmatrix source addresses (per-lane), relative to tile base
    const uint32_t a_lrow = (lane & 15);
    const uint32_t a_koff = (lane >> 4) * 16;     // bytes

    for (int c = 0; c < nchunk; ++c) {
        const uint32_t buf = sbase + (uint32_t)(c & 1) * BUF_B;

        // store chunk c
        #pragma unroll
        for (int i = 0; i < 4; i++) {
            const uint32_t off = (uint32_t)(gr + i * 32) * ROWB + gc4 * 8;
            split_store(buf + AHI_OFF + off, buf + ALO_OFF + off, pa[i]);
            split_store(buf + BHI_OFF + off, buf + BLO_OFF + off, pb[i]);
        }
        __syncthreads();

        // prefetch chunk c+1
        if (c + 1 < nchunk) {
            const int kc = (c + 1) * 32;
            #pragma unroll
            for (int i = 0; i < 4; i++) {
                const int r = gr + i * 32;
                pa[i] = *(const float4*)&A[(size_t)(bm + r) * K + kc + gc4 * 4];
                pb[i] = *(const float4*)&B[(size_t)(bn + r) * K + kc + gc4 * 4];
            }
        }

        // compute chunk c: 2 k16 steps
        #pragma unroll
        for (int ks = 0; ks < 2; ks++) {
            const uint32_t kb = ks * 32 + a_koff;   // byte offset in row

            uint32_t ah[2][4], al[2][4];
            #pragma unroll
            for (int mt = 0; mt < 2; mt++) {
                const uint32_t rowoff = (uint32_t)(m0 + mt * 16 + a_lrow) * ROWB + kb;
                ldsm_x4(ah[mt], buf + AHI_OFF + rowoff);
                ldsm_x4(al[mt], buf + ALO_OFF + rowoff);
            }
            uint32_t bh[4][4], bl[4][4];
            #pragma unroll
            for (int g = 0; g < 4; g++) {
                const uint32_t rowoff = (uint32_t)(n0 + g * 16 + a_lrow) * ROWB + kb;
                ldsm_x4(bh[g], buf + BHI_OFF + rowoff);
                ldsm_x4(bl[g], buf + BLO_OFF + rowoff);
            }

            #pragma unroll
            for (int mt = 0; mt < 2; mt++) {
                #pragma unroll
                for (int g = 0; g < 4; g++) {
                    // fragment g*2   : b regs {r0, r2}
                    // fragment g*2+1 : b regs {r1, r3}
                    mma_bf16(acc[mt][g * 2 + 0], ah[mt], bh[g][0], bh[g][2]);
                    mma_bf16(acc[mt][g * 2 + 0], ah[mt], bl[g][0], bl[g][2]);
                    mma_bf16(acc[mt][g * 2 + 0], al[mt], bh[g][0], bh[g][2]);
                    mma_bf16(acc[mt][g * 2 + 1], ah[mt], bh[g][1], bh[g][3]);
                    mma_bf16(acc[mt][g * 2 + 1], ah[mt], bl[g][1], bl[g][3]);
                    mma_bf16(acc[mt][g * 2 + 1], al[mt], bh[g][1], bh[g][3]);
                }
            }
        }
    }

    // epilogue: natural layout, coalesced float2 stores
    #pragma unroll
    for (int mt = 0; mt < 2; mt++) {
        const int row = bm + m0 + mt * 16 + (lane >> 2);
        #pragma unroll
        for (int nf = 0; nf < 8; nf++) {
            const int col = bn + n0 + nf * 8 + (lane & 3) * 2;
            float2 v0 = make_float2(acc[mt][nf][0], acc[mt][nf][1]);
            float2 v1 = make_float2(acc[mt][nf][2], acc[mt][nf][3]);
            *(float2*)&C[(size_t)row * N + col]       = v0;
            *(float2*)&C[(size_t)(row + 8) * N + col] = v1;
        }
    }
}

// ---------------------------------------------------------------------------
// Causal flash attention, fp32 (unchanged from R1 baseline).
// ---------------------------------------------------------------------------
#define QS_OFF 0
#define KS_OFF (64 * 68)
#define SS_OFF (2 * 64 * 68)
#define VS_OFF (3 * 64 * 68)
#define ATTN_SMEM_BYTES ((3 * 64 * 68 + 64 * 64) * 4)

__global__ __launch_bounds__(256)
void attn_kernel()
{
    extern __shared__ float sm[];
    float* Qs = sm + QS_OFF;
    float* Ks = sm + KS_OFF;
    float* Ss = sm + SS_OFF;
    float* Vs = sm + VS_OFF;

    const int tid = threadIdx.x;
    const int tx = tid & 15;
    const int ty = tid >> 4;
    const int qb = blockIdx.x;
    const int h  = blockIdx.y;
    const float scale = 0.125f;

    #pragma unroll
    for (int r = 0; r < 4; r++) {
        int idx = tid + r * 256;
        int d = idx >> 4, seg = (idx & 15) * 4;
        float4 v = *(const float4*)&g_Q[(size_t)(h * 64 + d) * S_LEN + qb * 64 + seg];
        *(float4*)&Qs[d * 68 + seg] = v;
    }

    float m_i[4], l_i[4], o[4][4];
    #pragma unroll
    for (int i = 0; i < 4; i++) {
        m_i[i] = -1e30f; l_i[i] = 0.0f;
        #pragma unroll
        for (int d = 0; d < 4; d++) o[i][d] = 0.0f;
    }

    for (int kb = 0; kb <= qb; ++kb) {
        __syncthreads();

        #pragma unroll
        for (int r = 0; r < 4; r++) {
            int idx = tid + r * 256;
            int d = idx >> 4, seg = (idx & 15) * 4;
            float4 kv = *(const float4*)&g_K[(size_t)(h * 64 + d) * S_LEN + kb * 64 + seg];
            *(float4*)&Ks[d * 68 + seg] = kv;
            int j = d;
            float4 vv = *(const float4*)&g_V[(size_t)(kb * 64 + j) * DM + h * 64 + seg];
            *(float4*)&Vs[j * 64 + seg] = vv;
        }
        __syncthreads();

        float sacc[4][4];
        #pragma unroll
        for (int i = 0; i < 4; i++)
            #pragma unroll
            for (int j = 0; j < 4; j++) sacc[i][j] = 0.0f;

        #pragma unroll 8
        for (int d = 0; d < 64; d++) {
            float4 a = *(const float4*)&Qs[d * 68 + ty * 4];
            float4 b = *(const float4*)&Ks[d * 68 + tx * 4];
            float av[4] = {a.x, a.y, a.z, a.w};
            float bv[4] = {b.x, b.y, b.z, b.w};
            #pragma unroll
            for (int i = 0; i < 4; i++)
                #pragma unroll
                for (int j = 0; j < 4; j++)
                    sacc[i][j] = fmaf(av[i], bv[j], sacc[i][j]);
        }

        if (kb == qb) {
            #pragma unroll
            for (int i = 0; i < 4; i++) {
                int row = qb * 64 + ty * 4 + i;
                #pragma unroll
                for (int j = 0; j < 4; j++) {
                    int col = kb * 64 + tx * 4 + j;
                    sacc[i][j] = (col > row) ? -1e30f : sacc[i][j] * scale;
                }
            }
        } else {
            #pragma unroll
            for (int i = 0; i < 4; i++)
                #pragma unroll
                for (int j = 0; j < 4; j++) sacc[i][j] *= scale;
        }

        #pragma unroll
        for (int i = 0; i < 4; i++) {
            float rm = fmaxf(fmaxf(sacc[i][0], sacc[i][1]), fmaxf(sacc[i][2], sacc[i][3]));
            #pragma unroll
            for (int off = 1; off < 16; off <<= 1)
                rm = fmaxf(rm, __shfl_xor_sync(0xffffffffu, rm, off));
            float m_new = fmaxf(m_i[i], rm);
            float alpha = __expf(m_i[i] - m_new);
            float rs = 0.0f;
            #pragma unroll
            for (int j = 0; j < 4; j++) {
                sacc[i][j] = __expf(sacc[i][j] - m_new);
                rs += sacc[i][j];
            }
            #pragma unroll
            for (int off = 1; off < 16; off <<= 1)
                rs += __shfl_xor_sync(0xffffffffu, rs, off);
            l_i[i] = l_i[i] * alpha + rs;
            m_i[i] = m_new;
            #pragma unroll
            for (int d = 0; d < 4; d++) o[i][d] *= alpha;
            *(float4*)&Ss[(ty * 4 + i) * 68 + tx * 4] =
                make_float4(sacc[i][0], sacc[i][1], sacc[i][2], sacc[i][3]);
        }
        __syncthreads();

        #pragma unroll 4
        for (int j = 0; j < 64; j++) {
            float4 v = *(const float4*)&Vs[j * 64 + tx * 4];
            float vv[4] = {v.x, v.y, v.z, v.w};
            #pragma unroll
            for (int i = 0; i < 4; i++) {
                float p = Ss[(ty * 4 + i) * 68 + j];
                #pragma unroll
                for (int d = 0; d < 4; d++)
                    o[i][d] = fmaf(p, vv[d], o[i][d]);
            }
        }
    }

    #pragma unroll
    for (int i = 0; i < 4; i++) {
        float inv = 1.0f / l_i[i];
        float4 v = make_float4(o[i][0] * inv, o[i][1] * inv, o[i][2] * inv, o[i][3] * inv);
        *(float4*)&g_ctx[(size_t)(qb * 64 + ty * 4 + i) * DM + h * 64 + tx * 4] = v;
    }
}

// ---------------------------------------------------------------------------
extern "C" void kernel_launch(void* const* d_in, const int* in_sizes, int n_in,
                              void* d_out, int out_size)
{
    const float* x  = (const float*)d_in[0];
    const float* Wq = (const float*)d_in[1];
    const float* Wk = (const float*)d_in[2];
    const float* Wv = (const float*)d_in[3];
    const float* Wo = (const float*)d_in[4];
    float* out = (float*)d_out;

    float *pQ, *pK, *pV, *pC;
    cudaGetSymbolAddress((void**)&pQ, g_Q);
    cudaGetSymbolAddress((void**)&pK, g_K);
    cudaGetSymbolAddress((void**)&pV, g_V);
    cudaGetSymbolAddress((void**)&pC, g_ctx);

    cudaFuncSetAttribute(attn_kernel,
                         cudaFuncAttributeMaxDynamicSharedMemorySize,
                         ATTN_SMEM_BYTES);
    cudaFuncSetAttribute(gemm_bf16x3,
                         cudaFuncAttributeMaxDynamicSharedMemorySize,
                         GEMM_SMEM);

    // Q^T[hd][s] = Wq @ x^T :  gemm(A=Wq, B=x)   M=768,  N=4096
    gemm_bf16x3<<<dim3(DM / 128, S_LEN / 128), 256, GEMM_SMEM>>>(Wq, x, pQ, DM, S_LEN, DM);
    gemm_bf16x3<<<dim3(DM / 128, S_LEN / 128), 256, GEMM_SMEM>>>(Wk, x, pK, DM, S_LEN, DM);
    // V[s][hd] = x @ Wv^T :  M=4096, N=768
    gemm_bf16x3<<<dim3(S_LEN / 128, DM / 128), 256, GEMM_SMEM>>>(x, Wv, pV, S_LEN, DM, DM);

    attn_kernel<<<dim3(S_LEN / 64, NH), 256, ATTN_SMEM_BYTES>>>();

    // out = ctx @ Wo^T : M=4096, N=768
    gemm_bf16x3<<<dim3(S_LEN / 128, DM / 128), 256, GEMM_SMEM>>>(pC, Wo, out, S_LEN, DM, DM);
}

// round 4
// speedup vs baseline: 2.3865x; 1.8922x over previous
#include <cuda_runtime.h>
#include <cuda_bf16.h>
#include <cstdint>

#define S_LEN 4096
#define DM    768
#define NH    12
#define DK    64

// Scratch (device globals — no allocation allowed in kernel_launch)
__device__ __nv_bfloat16 g_Qh[S_LEN * DM];   // [s][hd]
__device__ __nv_bfloat16 g_Ql[S_LEN * DM];
__device__ __nv_bfloat16 g_Kh[S_LEN * DM];   // [s][hd]
__device__ __nv_bfloat16 g_Kl[S_LEN * DM];
__device__ __nv_bfloat16 g_Vth[DM * S_LEN];  // [hd][s]  (V transposed per head)
__device__ __nv_bfloat16 g_Vtl[DM * S_LEN];
__device__ float g_ctx[S_LEN * DM];          // attention output, natural fp32

// ===========================================================================
// helpers
// ===========================================================================
__device__ __forceinline__ uint32_t smem_u32(const void* p) {
    uint32_t a;
    asm("{ .reg .u64 t; cvta.to.shared.u64 t, %1; cvt.u32.u64 %0, t; }"
        : "=r"(a) : "l"(p));
    return a;
}

__device__ __forceinline__ void ldsm_x4(uint32_t* r, uint32_t addr) {
    asm volatile("ldmatrix.sync.aligned.m8n8.x4.shared.b16 {%0,%1,%2,%3}, [%4];"
                 : "=r"(r[0]), "=r"(r[1]), "=r"(r[2]), "=r"(r[3]) : "r"(addr));
}

__device__ __forceinline__ void mma_bf16(float* d, const uint32_t* a,
                                         uint32_t b0, uint32_t b1) {
    asm volatile("mma.sync.aligned.m16n8k16.row.col.f32.bf16.bf16.f32 "
                 "{%0,%1,%2,%3}, {%4,%5,%6,%7}, {%8,%9}, {%0,%1,%2,%3};"
                 : "+f"(d[0]), "+f"(d[1]), "+f"(d[2]), "+f"(d[3])
                 : "r"(a[0]), "r"(a[1]), "r"(a[2]), "r"(a[3]), "r"(b0), "r"(b1));
}

__device__ __forceinline__ void sts_v2(uint32_t addr, uint32_t a, uint32_t b) {
    asm volatile("st.shared.v2.b32 [%0], {%1, %2};" :: "r"(addr), "r"(a), "r"(b)
                 : "memory");
}
__device__ __forceinline__ void sts_v4(uint32_t addr, uint4 v) {
    asm volatile("st.shared.v4.b32 [%0], {%1, %2, %3, %4};"
                 :: "r"(addr), "r"(v.x), "r"(v.y), "r"(v.z), "r"(v.w) : "memory");
}

__device__ __forceinline__ uint32_t pack_bf16(float x, float y) {
    __nv_bfloat162 t = {__float2bfloat16(x), __float2bfloat16(y)};
    return *(uint32_t*)&t;
}
// split two floats into hi/lo bf16x2 words
__device__ __forceinline__ void split2(float x, float y, uint32_t& hi, uint32_t& lo) {
    __nv_bfloat16 hx = __float2bfloat16(x), hy = __float2bfloat16(y);
    __nv_bfloat162 h2 = {hx, hy};
    hi = *(uint32_t*)&h2;
    __nv_bfloat162 l2 = {__float2bfloat16(x - __bfloat162float(hx)),
                         __float2bfloat16(y - __bfloat162float(hy))};
    lo = *(uint32_t*)&l2;
}

// split fp32x4 into hi/lo bf16x2 pairs and store to smem (8B each)
__device__ __forceinline__ void split_store(uint32_t hi_addr, uint32_t lo_addr, float4 v) {
    uint32_t h0, l0, h1, l1;
    split2(v.x, v.y, h0, l0);
    split2(v.z, v.w, h1, l1);
    sts_v2(hi_addr, h0, h1);
    sts_v2(lo_addr, l0, l1);
}

// ===========================================================================
// bf16x3 tensor-core GEMM: C[M,N] = A[M,K] @ B[N,K]^T  (natural output)
// OMODE 0: write fp32 C.  OMODE 1: write bf16 hi/lo pair (Ch, Cl).
// 128x128 CTA tile, BK=32, 256 threads, warp grid 4(M)x2(N).
// ===========================================================================
#define ROWB      80
#define TILE_B    (128 * ROWB)
#define AHI_OFF   0
#define ALO_OFF   (1 * TILE_B)
#define BHI_OFF   (2 * TILE_B)
#define BLO_OFF   (3 * TILE_B)
#define BUF_B     (4 * TILE_B)
#define GEMM_SMEM (2 * BUF_B)

template<int OMODE>
__global__ __launch_bounds__(256)
void gemm_bf16x3(const float* __restrict__ A, const float* __restrict__ B,
                 float* __restrict__ C,
                 __nv_bfloat16* __restrict__ Ch, __nv_bfloat16* __restrict__ Cl,
                 int M, int N, int K)
{
    extern __shared__ __align__(128) char dynsm[];
    const uint32_t sbase = smem_u32(dynsm);

    const int tid  = threadIdx.x;
    const int lane = tid & 31;
    const int warp = tid >> 5;
    const int wm = warp >> 1;
    const int wn = warp & 1;
    const int m0 = wm * 32;
    const int n0 = wn * 64;
    const int bm = blockIdx.x * 128;
    const int bn = blockIdx.y * 128;

    const int gr  = tid >> 3;
    const int gc4 = tid & 7;

    float acc[2][8][4];
    #pragma unroll
    for (int mt = 0; mt < 2; mt++)
        #pragma unroll
        for (int nf = 0; nf < 8; nf++)
            #pragma unroll
            for (int e = 0; e < 4; e++) acc[mt][nf][e] = 0.0f;

    const int nchunk = K / 32;

    float4 pa[4], pb[4];
    #pragma unroll
    for (int i = 0; i < 4; i++) {
        const int r = gr + i * 32;
        pa[i] = *(const float4*)&A[(size_t)(bm + r) * K + gc4 * 4];
        pb[i] = *(const float4*)&B[(size_t)(bn + r) * K + gc4 * 4];
    }

    const uint32_t a_lrow = (lane & 15);
    const uint32_t a_koff = (lane >> 4) * 16;

    for (int c = 0; c < nchunk; ++c) {
        const uint32_t buf = sbase + (uint32_t)(c & 1) * BUF_B;

        #pragma unroll
        for (int i = 0; i < 4; i++) {
            const uint32_t off = (uint32_t)(gr + i * 32) * ROWB + gc4 * 8;
            split_store(buf + AHI_OFF + off, buf + ALO_OFF + off, pa[i]);
            split_store(buf + BHI_OFF + off, buf + BLO_OFF + off, pb[i]);
        }
        __syncthreads();

        if (c + 1 < nchunk) {
            const int kc = (c + 1) * 32;
            #pragma unroll
            for (int i = 0; i < 4; i++) {
                const int r = gr + i * 32;
                pa[i] = *(const float4*)&A[(size_t)(bm + r) * K + kc + gc4 * 4];
                pb[i] = *(const float4*)&B[(size_t)(bn + r) * K + kc + gc4 * 4];
            }
        }

        #pragma unroll
        for (int ks = 0; ks < 2; ks++) {
            const uint32_t kb = ks * 32 + a_koff;

            uint32_t ah[2][4], al[2][4];
            #pragma unroll
            for (int mt = 0; mt < 2; mt++) {
                const uint32_t rowoff = (uint32_t)(m0 + mt * 16 + a_lrow) * ROWB + kb;
                ldsm_x4(ah[mt], buf + AHI_OFF + rowoff);
                ldsm_x4(al[mt], buf + ALO_OFF + rowoff);
            }
            uint32_t bh[4][4], bl[4][4];
            #pragma unroll
            for (int g = 0; g < 4; g++) {
                const uint32_t rowoff = (uint32_t)(n0 + g * 16 + a_lrow) * ROWB + kb;
                ldsm_x4(bh[g], buf + BHI_OFF + rowoff);
                ldsm_x4(bl[g], buf + BLO_OFF + rowoff);
            }

            #pragma unroll
            for (int mt = 0; mt < 2; mt++) {
                #pragma unroll
                for (int g = 0; g < 4; g++) {
                    mma_bf16(acc[mt][g * 2 + 0], ah[mt], bh[g][0], bh[g][2]);
                    mma_bf16(acc[mt][g * 2 + 0], ah[mt], bl[g][0], bl[g][2]);
                    mma_bf16(acc[mt][g * 2 + 0], al[mt], bh[g][0], bh[g][2]);
                    mma_bf16(acc[mt][g * 2 + 1], ah[mt], bh[g][1], bh[g][3]);
                    mma_bf16(acc[mt][g * 2 + 1], ah[mt], bl[g][1], bl[g][3]);
                    mma_bf16(acc[mt][g * 2 + 1], al[mt], bh[g][1], bh[g][3]);
                }
            }
        }
    }

    #pragma unroll
    for (int mt = 0; mt < 2; mt++) {
        const int row = bm + m0 + mt * 16 + (lane >> 2);
        #pragma unroll
        for (int nf = 0; nf < 8; nf++) {
            const int col = bn + n0 + nf * 8 + (lane & 3) * 2;
            if (OMODE == 0) {
                *(float2*)&C[(size_t)row * N + col] =
                    make_float2(acc[mt][nf][0], acc[mt][nf][1]);
                *(float2*)&C[(size_t)(row + 8) * N + col] =
                    make_float2(acc[mt][nf][2], acc[mt][nf][3]);
            } else {
                uint32_t h0, l0, h1, l1;
                split2(acc[mt][nf][0], acc[mt][nf][1], h0, l0);
                split2(acc[mt][nf][2], acc[mt][nf][3], h1, l1);
                *(uint32_t*)&Ch[(size_t)row * N + col]       = h0;
                *(uint32_t*)&Cl[(size_t)row * N + col]       = l0;
                *(uint32_t*)&Ch[(size_t)(row + 8) * N + col] = h1;
                *(uint32_t*)&Cl[(size_t)(row + 8) * N + col] = l1;
            }
        }
    }
}

// ===========================================================================
// Tensor-core causal flash attention (bf16x3).
// CTA = (head, 128-query tile), 8 warps (16 rows each), 64-key tiles.
// smem: Qh/Ql [128][72]bf16, Kh/Kl [64][72], Vth/Vtl [64][72] (rows padded).
// ===========================================================================
#define AROWB 144                 // 72 bf16 per padded row
#define AQH 0
#define AQL (AQH + 128 * AROWB)   // 18432
#define AKH (AQL + 128 * AROWB)   // 36864
#define AKL (AKH + 64 * AROWB)    // 46080
#define AVH (AKL + 64 * AROWB)    // 55296
#define AVL (AVH + 64 * AROWB)    // 64512
#define ATTN_SMEM (AVL + 64 * AROWB)  // 73728

__global__ __launch_bounds__(256, 2)
void attn_tc()
{
    extern __shared__ __align__(128) char dynbuf[];
    const uint32_t sb = smem_u32(dynbuf);

    const int tid  = threadIdx.x;
    const int lane = tid & 31;
    const int warp = tid >> 5;
    const int wr   = warp * 16;                 // warp's query-row base in tile
    const int qb   = (int)gridDim.x - 1 - (int)blockIdx.x;  // heavy CTAs first
    const int h    = blockIdx.y;
    const int q0   = qb * 128;

    const int gr = tid >> 3;                    // 0..31 row step
    const int gc = tid & 7;                     // float4 column

    // ---- load Q tile (hi/lo) once ----
    #pragma unroll
    for (int i = 0; i < 4; i++) {
        const int r = gr + i * 32;              // 0..127
        const uint32_t soff = (uint32_t)r * AROWB + gc * 16;
        uint4 vh = *(const uint4*)&g_Qh[(size_t)(q0 + r) * DM + h * 64 + gc * 8];
        uint4 vl = *(const uint4*)&g_Ql[(size_t)(q0 + r) * DM + h * 64 + gc * 8];
        sts_v4(sb + AQH + soff, vh);
        sts_v4(sb + AQL + soff, vl);
    }

    float o[8][4];
    #pragma unroll
    for (int f = 0; f < 8; f++)
        #pragma unroll
        for (int e = 0; e < 4; e++) o[f][e] = 0.0f;
    float m_s[2] = {-1e30f, -1e30f};
    float l_s[2] = {0.0f, 0.0f};

    const int row0 = q0 + wr + (lane >> 2);
    const int row1 = row0 + 8;
    const uint32_t lrow = (lane & 15);
    const uint32_t koff = (lane >> 4) * 16;
    const int ntile = 2 * qb + 2;

    for (int t = 0; t < ntile; ++t) {
        const int k0 = t * 64;
        __syncthreads();   // Q store done (t=0) / prior mma reads done

        // ---- load K/V tiles (hi/lo) ----
        #pragma unroll
        for (int i = 0; i < 2; i++) {
            const int r = gr + i * 32;          // 0..63
            const uint32_t soff = (uint32_t)r * AROWB + gc * 16;
            uint4 kh = *(const uint4*)&g_Kh[(size_t)(k0 + r) * DM + h * 64 + gc * 8];
            uint4 kl = *(const uint4*)&g_Kl[(size_t)(k0 + r) * DM + h * 64 + gc * 8];
            sts_v4(sb + AKH + soff, kh);
            sts_v4(sb + AKL + soff, kl);
            uint4 vh = *(const uint4*)&g_Vth[(size_t)(h * 64 + r) * S_LEN + k0 + gc * 8];
            uint4 vl = *(const uint4*)&g_Vtl[(size_t)(h * 64 + r) * S_LEN + k0 + gc * 8];
            sts_v4(sb + AVH + soff, vh);
            sts_v4(sb + AVL + soff, vl);
        }
        __syncthreads();

        // ---- S = Q K^T (bf16x3) ----
        float sacc[8][4];
        #pragma unroll
        for (int f = 0; f < 8; f++)
            #pragma unroll
            for (int e = 0; e < 4; e++) sacc[f][e] = 0.0f;

        #pragma unroll
        for (int ks = 0; ks < 4; ks++) {
            const uint32_t kb = ks * 32 + koff;
            uint32_t qh[4], ql[4];
            const uint32_t qoff = (uint32_t)(wr + lrow) * AROWB + kb;
            ldsm_x4(qh, sb + AQH + qoff);
            ldsm_x4(ql, sb + AQL + qoff);
            #pragma unroll
            for (int g = 0; g < 4; g++) {
                uint32_t kh[4], kl[4];
                const uint32_t koff2 = (uint32_t)(g * 16 + lrow) * AROWB + kb;
                ldsm_x4(kh, sb + AKH + koff2);
                ldsm_x4(kl, sb + AKL + koff2);
                mma_bf16(sacc[g * 2 + 0], qh, kh[0], kh[2]);
                mma_bf16(sacc[g * 2 + 0], qh, kl[0], kl[2]);
                mma_bf16(sacc[g * 2 + 0], ql, kh[0], kh[2]);
                mma_bf16(sacc[g * 2 + 1], qh, kh[1], kh[3]);
                mma_bf16(sacc[g * 2 + 1], qh, kl[1], kl[3]);
                mma_bf16(sacc[g * 2 + 1], ql, kh[1], kh[3]);
            }
        }

        // ---- scale + causal mask ----
        const float scale = 0.125f;
        if (t >= 2 * qb) {
            #pragma unroll
            for (int f = 0; f < 8; f++) {
                const int cb = k0 + f * 8 + (lane & 3) * 2;
                sacc[f][0] = (cb     > row0) ? -1e30f : sacc[f][0] * scale;
                sacc[f][1] = (cb + 1 > row0) ? -1e30f : sacc[f][1] * scale;
                sacc[f][2] = (cb     > row1) ? -1e30f : sacc[f][2] * scale;
                sacc[f][3] = (cb + 1 > row1) ? -1e30f : sacc[f][3] * scale;
            }
        } else {
            #pragma unroll
            for (int f = 0; f < 8; f++)
                #pragma unroll
                for (int e = 0; e < 4; e++) sacc[f][e] *= scale;
        }

        // ---- online softmax (rows row0, row1) ----
        float rm0 = -1e30f, rm1 = -1e30f;
        #pragma unroll
        for (int f = 0; f < 8; f++) {
            rm0 = fmaxf(rm0, fmaxf(sacc[f][0], sacc[f][1]));
            rm1 = fmaxf(rm1, fmaxf(sacc[f][2], sacc[f][3]));
        }
        #pragma unroll
        for (int off = 1; off < 4; off <<= 1) {
            rm0 = fmaxf(rm0, __shfl_xor_sync(0xffffffffu, rm0, off));
            rm1 = fmaxf(rm1, __shfl_xor_sync(0xffffffffu, rm1, off));
        }
        const float mn0 = fmaxf(m_s[0], rm0);
        const float mn1 = fmaxf(m_s[1], rm1);
        const float al0 = __expf(m_s[0] - mn0);
        const float al1 = __expf(m_s[1] - mn1);
        float rs0 = 0.0f, rs1 = 0.0f;
        #pragma unroll
        for (int f = 0; f < 8; f++) {
            sacc[f][0] = __expf(sacc[f][0] - mn0);
            sacc[f][1] = __expf(sacc[f][1] - mn0);
            sacc[f][2] = __expf(sacc[f][2] - mn1);
            sacc[f][3] = __expf(sacc[f][3] - mn1);
            rs0 += sacc[f][0] + sacc[f][1];
            rs1 += sacc[f][2] + sacc[f][3];
        }
        #pragma unroll
        for (int off = 1; off < 4; off <<= 1) {
            rs0 += __shfl_xor_sync(0xffffffffu, rs0, off);
            rs1 += __shfl_xor_sync(0xffffffffu, rs1, off);
        }
        l_s[0] = l_s[0] * al0 + rs0;
        l_s[1] = l_s[1] * al1 + rs1;
        m_s[0] = mn0;
        m_s[1] = mn1;
        #pragma unroll
        for (int f = 0; f < 8; f++) {
            o[f][0] *= al0; o[f][1] *= al0;
            o[f][2] *= al1; o[f][3] *= al1;
        }

        // ---- O += P V (bf16x3; P from accumulator fragments) ----
        #pragma unroll
        for (int ks = 0; ks < 4; ks++) {
            const float* s0 = sacc[2 * ks];
            const float* s1 = sacc[2 * ks + 1];
            uint32_t ph[4], pl[4];
            split2(s0[0], s0[1], ph[0], pl[0]);
            split2(s0[2], s0[3], ph[1], pl[1]);
            split2(s1[0], s1[1], ph[2], pl[2]);
            split2(s1[2], s1[3], ph[3], pl[3]);
            const uint32_t kb = ks * 32 + koff;
            #pragma unroll
            for (int g = 0; g < 4; g++) {
                uint32_t vh[4], vl[4];
                const uint32_t voff = (uint32_t)(g * 16 + lrow) * AROWB + kb;
                ldsm_x4(vh, sb + AVH + voff);
                ldsm_x4(vl, sb + AVL + voff);
                mma_bf16(o[g * 2 + 0], ph, vh[0], vh[2]);
                mma_bf16(o[g * 2 + 0], pl, vh[0], vh[2]);
                mma_bf16(o[g * 2 + 0], ph, vl[0], vl[2]);
                mma_bf16(o[g * 2 + 1], ph, vh[1], vh[3]);
                mma_bf16(o[g * 2 + 1], pl, vh[1], vh[3]);
                mma_bf16(o[g * 2 + 1], ph, vl[1], vl[3]);
            }
        }
    }

    // ---- normalize + write ctx ----
    const float inv0 = 1.0f / l_s[0];
    const float inv1 = 1.0f / l_s[1];
    #pragma unroll
    for (int f = 0; f < 8; f++) {
        const int col = h * 64 + f * 8 + (lane & 3) * 2;
        *(float2*)&g_ctx[(size_t)row0 * DM + col] =
            make_float2(o[f][0] * inv0, o[f][1] * inv0);
        *(float2*)&g_ctx[(size_t)row1 * DM + col] =
            make_float2(o[f][2] * inv1, o[f][3] * inv1);
    }
}

// ---------------------------------------------------------------------------
extern "C" void kernel_launch(void* const* d_in, const int* in_sizes, int n_in,
                              void* d_out, int out_size)
{
    const float* x  = (const float*)d_in[0];
    const float* Wq = (const float*)d_in[1];
    const float* Wk = (const float*)d_in[2];
    const float* Wv = (const float*)d_in[3];
    const float* Wo = (const float*)d_in[4];
    float* out = (float*)d_out;

    float* pC;
    __nv_bfloat16 *pQh, *pQl, *pKh, *pKl, *pVth, *pVtl;
    cudaGetSymbolAddress((void**)&pC,   g_ctx);
    cudaGetSymbolAddress((void**)&pQh,  g_Qh);
    cudaGetSymbolAddress((void**)&pQl,  g_Ql);
    cudaGetSymbolAddress((void**)&pKh,  g_Kh);
    cudaGetSymbolAddress((void**)&pKl,  g_Kl);
    cudaGetSymbolAddress((void**)&pVth, g_Vth);
    cudaGetSymbolAddress((void**)&pVtl, g_Vtl);

    cudaFuncSetAttribute(gemm_bf16x3<0>,
                         cudaFuncAttributeMaxDynamicSharedMemorySize, GEMM_SMEM);
    cudaFuncSetAttribute(gemm_bf16x3<1>,
                         cudaFuncAttributeMaxDynamicSharedMemorySize, GEMM_SMEM);
    cudaFuncSetAttribute(attn_tc,
                         cudaFuncAttributeMaxDynamicSharedMemorySize, ATTN_SMEM);

    // Q[s][hd], K[s][hd] natural; V^T[hd][s] via swapped operands
    gemm_bf16x3<1><<<dim3(S_LEN / 128, DM / 128), 256, GEMM_SMEM>>>(
        x, Wq, nullptr, pQh, pQl, S_LEN, DM, DM);
    gemm_bf16x3<1><<<dim3(S_LEN / 128, DM / 128), 256, GEMM_SMEM>>>(
        x, Wk, nullptr, pKh, pKl, S_LEN, DM, DM);
    gemm_bf16x3<1><<<dim3(DM / 128, S_LEN / 128), 256, GEMM_SMEM>>>(
        Wv, x, nullptr, pVth, pVtl, DM, S_LEN, DM);

    attn_tc<<<dim3(S_LEN / 128, NH), 256, ATTN_SMEM>>>();

    gemm_bf16x3<0><<<dim3(S_LEN / 128, DM / 128), 256, GEMM_SMEM>>>(
        pC, Wo, out, nullptr, nullptr, S_LEN, DM, DM);
}

// round 5
// speedup vs baseline: 2.4807x; 1.0395x over previous
#include <cuda_runtime.h>
#include <cuda_bf16.h>
#include <cstdint>

#define S_LEN 4096
#define DM    768
#define NH    12
#define DK    64

// ---------------- scratch (device globals) ----------------
__device__ __nv_bfloat16 g_xh[S_LEN * DM],  g_xl[S_LEN * DM];
__device__ __nv_bfloat16 g_Wqh[DM * DM],    g_Wql[DM * DM];
__device__ __nv_bfloat16 g_Wkh[DM * DM],    g_Wkl[DM * DM];
__device__ __nv_bfloat16 g_Wvh[DM * DM],    g_Wvl[DM * DM];
__device__ __nv_bfloat16 g_Woh[DM * DM],    g_Wol[DM * DM];
__device__ __nv_bfloat16 g_Qh[S_LEN * DM],  g_Ql[S_LEN * DM];   // [s][hd]
__device__ __nv_bfloat16 g_Kh[S_LEN * DM],  g_Kl[S_LEN * DM];   // [s][hd]
__device__ __nv_bfloat16 g_Vth[DM * S_LEN], g_Vtl[DM * S_LEN];  // [hd][s]
__device__ __nv_bfloat16 g_ctxh[S_LEN * DM], g_ctxl[S_LEN * DM];

// ---------------- helpers ----------------
__device__ __forceinline__ uint32_t smem_u32(const void* p) {
    uint32_t a;
    asm("{ .reg .u64 t; cvta.to.shared.u64 t, %1; cvt.u32.u64 %0, t; }"
        : "=r"(a) : "l"(p));
    return a;
}
__device__ __forceinline__ void ldsm_x4(uint32_t* r, uint32_t addr) {
    asm volatile("ldmatrix.sync.aligned.m8n8.x4.shared.b16 {%0,%1,%2,%3}, [%4];"
                 : "=r"(r[0]), "=r"(r[1]), "=r"(r[2]), "=r"(r[3]) : "r"(addr));
}
__device__ __forceinline__ void mma_bf16(float* d, const uint32_t* a,
                                         uint32_t b0, uint32_t b1) {
    asm volatile("mma.sync.aligned.m16n8k16.row.col.f32.bf16.bf16.f32 "
                 "{%0,%1,%2,%3}, {%4,%5,%6,%7}, {%8,%9}, {%0,%1,%2,%3};"
                 : "+f"(d[0]), "+f"(d[1]), "+f"(d[2]), "+f"(d[3])
                 : "r"(a[0]), "r"(a[1]), "r"(a[2]), "r"(a[3]), "r"(b0), "r"(b1));
}
__device__ __forceinline__ void sts_v4(uint32_t addr, uint4 v) {
    asm volatile("st.shared.v4.b32 [%0], {%1, %2, %3, %4};"
                 :: "r"(addr), "r"(v.x), "r"(v.y), "r"(v.z), "r"(v.w) : "memory");
}
__device__ __forceinline__ void split2(float x, float y, uint32_t& hi, uint32_t& lo) {
    __nv_bfloat16 hx = __float2bfloat16(x), hy = __float2bfloat16(y);
    __nv_bfloat162 h2 = {hx, hy};
    hi = *(uint32_t*)&h2;
    __nv_bfloat162 l2 = {__float2bfloat16(x - __bfloat162float(hx)),
                         __float2bfloat16(y - __bfloat162float(hy))};
    lo = *(uint32_t*)&l2;
}
__device__ __forceinline__ void cp_async16(uint32_t dst, const void* src) {
    asm volatile("cp.async.cg.shared.global [%0], [%1], 16;"
                 :: "r"(dst), "l"(src));
}
#define CP_COMMIT() asm volatile("cp.async.commit_group;" ::: "memory")
#define CP_WAIT0()  asm volatile("cp.async.wait_group 0;" ::: "memory")

// ---------------- fp32 -> bf16 hi/lo split pass ----------------
__global__ __launch_bounds__(256)
void split_f32(const float* __restrict__ in, __nv_bfloat16* __restrict__ hi,
               __nv_bfloat16* __restrict__ lo, int n4)
{
    int i = blockIdx.x * blockDim.x + threadIdx.x;
    if (i >= n4) return;
    float4 v = ((const float4*)in)[i];
    uint32_t h0, l0, h1, l1;
    split2(v.x, v.y, h0, l0);
    split2(v.z, v.w, h1, l1);
    ((uint2*)hi)[i] = make_uint2(h0, h1);
    ((uint2*)lo)[i] = make_uint2(l0, l1);
}

// ===========================================================================
// bf16x3 GEMM, pre-split inputs: C = A[M,K] @ B[N,K]^T
// OMODE 0: fp32 C.  OMODE 1: bf16 hi/lo (Ch, Cl).
// 128x128 tile, BK=32, 256 threads, cp.async double buffer.
// ===========================================================================
#define ROWB      80
#define TILE_B    (128 * ROWB)
#define BUF_B     (4 * TILE_B)
#define GEMM_SMEM (2 * BUF_B)

template<int OMODE>
__global__ __launch_bounds__(256)
void gemm_pre(const __nv_bfloat16* __restrict__ Ah, const __nv_bfloat16* __restrict__ Al,
              const __nv_bfloat16* __restrict__ Bh, const __nv_bfloat16* __restrict__ Bl,
              float* __restrict__ C,
              __nv_bfloat16* __restrict__ Ch, __nv_bfloat16* __restrict__ Cl,
              int M, int N, int K)
{
    extern __shared__ __align__(128) char dynsm[];
    const uint32_t sbase = smem_u32(dynsm);

    const int tid  = threadIdx.x;
    const int lane = tid & 31;
    const int warp = tid >> 5;
    const int m0 = (warp >> 1) * 32;
    const int n0 = (warp & 1) * 64;
    const int bm = blockIdx.x * 128;
    const int bn = blockIdx.y * 128;

    float acc[2][8][4];
    #pragma unroll
    for (int mt = 0; mt < 2; mt++)
        #pragma unroll
        for (int nf = 0; nf < 8; nf++)
            #pragma unroll
            for (int e = 0; e < 4; e++) acc[mt][nf][e] = 0.0f;

    const int nchunk = K / 32;

    // cp.async loader: idx = tid + j*256; tile=idx>>9; row=(idx&511)>>2; ch=idx&3
    auto issue = [&](int c) {
        const uint32_t buf = sbase + (uint32_t)(c & 1) * BUF_B;
        const int kc = c * 32;
        #pragma unroll
        for (int j = 0; j < 8; j++) {
            const int idx = tid + j * 256;
            const int tile = idx >> 9;
            const int rem  = idx & 511;
            const int row  = rem >> 2;
            const int ch   = rem & 3;
            const uint32_t dst = buf + (uint32_t)tile * TILE_B + row * ROWB + ch * 16;
            const __nv_bfloat16* src;
            if (tile == 0)      src = &Ah[(size_t)(bm + row) * K + kc + ch * 8];
            else if (tile == 1) src = &Al[(size_t)(bm + row) * K + kc + ch * 8];
            else if (tile == 2) src = &Bh[(size_t)(bn + row) * K + kc + ch * 8];
            else                src = &Bl[(size_t)(bn + row) * K + kc + ch * 8];
            cp_async16(dst, src);
        }
        CP_COMMIT();
    };

    issue(0);

    const uint32_t lrow = (lane & 15);
    const uint32_t koff = (lane >> 4) * 16;

    for (int c = 0; c < nchunk; ++c) {
        CP_WAIT0();
        __syncthreads();
        if (c + 1 < nchunk) issue(c + 1);   // overlaps compute below

        const uint32_t buf = sbase + (uint32_t)(c & 1) * BUF_B;
        #pragma unroll
        for (int ks = 0; ks < 2; ks++) {
            const uint32_t kb = ks * 32 + koff;
            uint32_t ah[2][4], al[2][4];
            #pragma unroll
            for (int mt = 0; mt < 2; mt++) {
                const uint32_t ro = (uint32_t)(m0 + mt * 16 + lrow) * ROWB + kb;
                ldsm_x4(ah[mt], buf + 0 * TILE_B + ro);
                ldsm_x4(al[mt], buf + 1 * TILE_B + ro);
            }
            uint32_t bh[4][4], bl[4][4];
            #pragma unroll
            for (int g = 0; g < 4; g++) {
                const uint32_t ro = (uint32_t)(n0 + g * 16 + lrow) * ROWB + kb;
                ldsm_x4(bh[g], buf + 2 * TILE_B + ro);
                ldsm_x4(bl[g], buf + 3 * TILE_B + ro);
            }
            #pragma unroll
            for (int mt = 0; mt < 2; mt++) {
                #pragma unroll
                for (int g = 0; g < 4; g++) {
                    mma_bf16(acc[mt][g * 2 + 0], ah[mt], bh[g][0], bh[g][2]);
                    mma_bf16(acc[mt][g * 2 + 0], ah[mt], bl[g][0], bl[g][2]);
                    mma_bf16(acc[mt][g * 2 + 0], al[mt], bh[g][0], bh[g][2]);
                    mma_bf16(acc[mt][g * 2 + 1], ah[mt], bh[g][1], bh[g][3]);
                    mma_bf16(acc[mt][g * 2 + 1], ah[mt], bl[g][1], bl[g][3]);
                    mma_bf16(acc[mt][g * 2 + 1], al[mt], bh[g][1], bh[g][3]);
                }
            }
        }
        __syncthreads();
    }

    #pragma unroll
    for (int mt = 0; mt < 2; mt++) {
        const int row = bm + m0 + mt * 16 + (lane >> 2);
        #pragma unroll
        for (int nf = 0; nf < 8; nf++) {
            const int col = bn + n0 + nf * 8 + (lane & 3) * 2;
            if (OMODE == 0) {
                *(float2*)&C[(size_t)row * N + col] =
                    make_float2(acc[mt][nf][0], acc[mt][nf][1]);
                *(float2*)&C[(size_t)(row + 8) * N + col] =
                    make_float2(acc[mt][nf][2], acc[mt][nf][3]);
            } else {
                uint32_t h0, l0, h1, l1;
                split2(acc[mt][nf][0], acc[mt][nf][1], h0, l0);
                split2(acc[mt][nf][2], acc[mt][nf][3], h1, l1);
                *(uint32_t*)&Ch[(size_t)row * N + col]       = h0;
                *(uint32_t*)&Cl[(size_t)row * N + col]       = l0;
                *(uint32_t*)&Ch[(size_t)(row + 8) * N + col] = h1;
                *(uint32_t*)&Cl[(size_t)(row + 8) * N + col] = l1;
            }
        }
    }
}

// ===========================================================================
// Tensor-core causal flash attention (bf16x3), cp.async double-buffered K/V.
// CTA = (head, 128 queries), 8 warps. Q: padded 144B rows (loaded once).
// K/V: 128B rows, XOR swizzle (c ^= row&7), 2 stages.
// ===========================================================================
#define AROWB 144
#define AQH   0
#define AQL   (128 * AROWB)          // 18432
#define AKV   (2 * 128 * AROWB)      // 36864
#define KVSTG 32768                  // 4 arrays x 64 x 128B
#define KH_O  0
#define KL_O  8192
#define VH_O  16384
#define VL_O  24576
#define ATTN_SMEM (AKV + 2 * KVSTG)  // 102400

__global__ __launch_bounds__(256, 2)
void attn_tc()
{
    extern __shared__ __align__(128) char dynbuf[];
    const uint32_t sb = smem_u32(dynbuf);

    const int tid  = threadIdx.x;
    const int lane = tid & 31;
    const int warp = tid >> 5;
    const int wr   = warp * 16;
    const int qb   = (int)gridDim.x - 1 - (int)blockIdx.x;
    const int h    = blockIdx.y;
    const int q0   = qb * 128;

    // ---- load Q tile (hi/lo) once: plain LDG + STS ----
    {
        const int gr = tid >> 3;
        const int gc = tid & 7;
        #pragma unroll
        for (int i = 0; i < 4; i++) {
            const int r = gr + i * 32;
            const uint32_t soff = (uint32_t)r * AROWB + gc * 16;
            uint4 vh = *(const uint4*)&g_Qh[(size_t)(q0 + r) * DM + h * 64 + gc * 8];
            uint4 vl = *(const uint4*)&g_Ql[(size_t)(q0 + r) * DM + h * 64 + gc * 8];
            sts_v4(sb + AQH + soff, vh);
            sts_v4(sb + AQL + soff, vl);
        }
    }

    // K/V cp.async loader for tile t (64 keys at k0)
    auto issue_kv = [&](int t) {
        const uint32_t kvb = sb + AKV + (uint32_t)(t & 1) * KVSTG;
        const int k0 = t * 64;
        #pragma unroll
        for (int j = 0; j < 8; j++) {
            const int idx = tid + j * 256;
            const int arr = idx >> 9;            // 0:Kh 1:Kl 2:Vh 3:Vl
            const int rem = idx & 511;
            const int row = rem >> 3;            // 0..63
            const int c   = rem & 7;             // 16B chunk
            const uint32_t dst = kvb + (uint32_t)arr * 8192 + row * 128 +
                                 ((uint32_t)(c ^ (row & 7)) << 4);
            const __nv_bfloat16* src;
            if (arr == 0)      src = &g_Kh[(size_t)(k0 + row) * DM + h * 64 + c * 8];
            else if (arr == 1) src = &g_Kl[(size_t)(k0 + row) * DM + h * 64 + c * 8];
            else if (arr == 2) src = &g_Vth[(size_t)(h * 64 + row) * S_LEN + k0 + c * 8];
            else               src = &g_Vtl[(size_t)(h * 64 + row) * S_LEN + k0 + c * 8];
            cp_async16(dst, src);
        }
        CP_COMMIT();
    };

    issue_kv(0);

    float o[8][4];
    #pragma unroll
    for (int f = 0; f < 8; f++)
        #pragma unroll
        for (int e = 0; e < 4; e++) o[f][e] = 0.0f;
    float m_s[2] = {-1e30f, -1e30f};
    float l_s[2] = {0.0f, 0.0f};

    const int row0 = q0 + wr + (lane >> 2);
    const int row1 = row0 + 8;
    const uint32_t lrow = (lane & 15);
    const uint32_t koff = (lane >> 4) * 16;
    const int ntile = 2 * qb + 2;

    for (int t = 0; t < ntile; ++t) {
        const int k0 = t * 64;
        CP_WAIT0();
        __syncthreads();                 // stage t ready + Q visible (t=0)
        if (t + 1 < ntile) issue_kv(t + 1);   // overlaps compute

        const uint32_t kvb = sb + AKV + (uint32_t)(t & 1) * KVSTG;

        // ---- S = Q K^T ----
        float sacc[8][4];
        #pragma unroll
        for (int f = 0; f < 8; f++)
            #pragma unroll
            for (int e = 0; e < 4; e++) sacc[f][e] = 0.0f;

        #pragma unroll
        for (int ks = 0; ks < 4; ks++) {
            uint32_t qh[4], ql[4];
            const uint32_t qoff = (uint32_t)(wr + lrow) * AROWB + ks * 32 + koff;
            ldsm_x4(qh, sb + AQH + qoff);
            ldsm_x4(ql, sb + AQL + qoff);
            const uint32_t cidx = ks * 2 + (lane >> 4);
            #pragma unroll
            for (int g = 0; g < 4; g++) {
                const uint32_t row = g * 16 + lrow;
                const uint32_t ro = row * 128 + ((cidx ^ (row & 7)) << 4);
                uint32_t kh[4], kl[4];
                ldsm_x4(kh, kvb + KH_O + ro);
                ldsm_x4(kl, kvb + KL_O + ro);
                mma_bf16(sacc[g * 2 + 0], qh, kh[0], kh[2]);
                mma_bf16(sacc[g * 2 + 0], qh, kl[0], kl[2]);
                mma_bf16(sacc[g * 2 + 0], ql, kh[0], kh[2]);
                mma_bf16(sacc[g * 2 + 1], qh, kh[1], kh[3]);
                mma_bf16(sacc[g * 2 + 1], qh, kl[1], kl[3]);
                mma_bf16(sacc[g * 2 + 1], ql, kh[1], kh[3]);
            }
        }

        // ---- scale + causal mask ----
        const float scale = 0.125f;
        if (t >= 2 * qb) {
            #pragma unroll
            for (int f = 0; f < 8; f++) {
                const int cb = k0 + f * 8 + (lane & 3) * 2;
                sacc[f][0] = (cb     > row0) ? -1e30f : sacc[f][0] * scale;
                sacc[f][1] = (cb + 1 > row0) ? -1e30f : sacc[f][1] * scale;
                sacc[f][2] = (cb     > row1) ? -1e30f : sacc[f][2] * scale;
                sacc[f][3] = (cb + 1 > row1) ? -1e30f : sacc[f][3] * scale;
            }
        } else {
            #pragma unroll
            for (int f = 0; f < 8; f++)
                #pragma unroll
                for (int e = 0; e < 4; e++) sacc[f][e] *= scale;
        }

        // ---- online softmax ----
        float rm0 = -1e30f, rm1 = -1e30f;
        #pragma unroll
        for (int f = 0; f < 8; f++) {
            rm0 = fmaxf(rm0, fmaxf(sacc[f][0], sacc[f][1]));
            rm1 = fmaxf(rm1, fmaxf(sacc[f][2], sacc[f][3]));
        }
        #pragma unroll
        for (int off = 1; off < 4; off <<= 1) {
            rm0 = fmaxf(rm0, __shfl_xor_sync(0xffffffffu, rm0, off));
            rm1 = fmaxf(rm1, __shfl_xor_sync(0xffffffffu, rm1, off));
        }
        const float mn0 = fmaxf(m_s[0], rm0);
        const float mn1 = fmaxf(m_s[1], rm1);
        const float al0 = __expf(m_s[0] - mn0);
        const float al1 = __expf(m_s[1] - mn1);
        float rs0 = 0.0f, rs1 = 0.0f;
        #pragma unroll
        for (int f = 0; f < 8; f++) {
            sacc[f][0] = __expf(sacc[f][0] - mn0);
            sacc[f][1] = __expf(sacc[f][1] - mn0);
            sacc[f][2] = __expf(sacc[f][2] - mn1);
            sacc[f][3] = __expf(sacc[f][3] - mn1);
            rs0 += sacc[f][0] + sacc[f][1];
            rs1 += sacc[f][2] + sacc[f][3];
        }
        #pragma unroll
        for (int off = 1; off < 4; off <<= 1) {
            rs0 += __shfl_xor_sync(0xffffffffu, rs0, off);
            rs1 += __shfl_xor_sync(0xffffffffu, rs1, off);
        }
        l_s[0] = l_s[0] * al0 + rs0;
        l_s[1] = l_s[1] * al1 + rs1;
        m_s[0] = mn0;
        m_s[1] = mn1;
        #pragma unroll
        for (int f = 0; f < 8; f++) {
            o[f][0] *= al0; o[f][1] *= al0;
            o[f][2] *= al1; o[f][3] *= al1;
        }

        // ---- O += P V (P split hi/lo) ----
        #pragma unroll
        for (int ks = 0; ks < 4; ks++) {
            const float* s0 = sacc[2 * ks];
            const float* s1 = sacc[2 * ks + 1];
            uint32_t ph[4], pl[4];
            split2(s0[0], s0[1], ph[0], pl[0]);
            split2(s0[2], s0[3], ph[1], pl[1]);
            split2(s1[0], s1[1], ph[2], pl[2]);
            split2(s1[2], s1[3], ph[3], pl[3]);
            const uint32_t cidx = ks * 2 + (lane >> 4);
            #pragma unroll
            for (int g = 0; g < 4; g++) {
                const uint32_t row = g * 16 + lrow;
                const uint32_t ro = row * 128 + ((cidx ^ (row & 7)) << 4);
                uint32_t vh[4], vl[4];
                ldsm_x4(vh, kvb + VH_O + ro);
                ldsm_x4(vl, kvb + VL_O + ro);
                mma_bf16(o[g * 2 + 0], ph, vh[0], vh[2]);
                mma_bf16(o[g * 2 + 0], pl, vh[0], vh[2]);
                mma_bf16(o[g * 2 + 0], ph, vl[0], vl[2]);
                mma_bf16(o[g * 2 + 1], ph, vh[1], vh[3]);
                mma_bf16(o[g * 2 + 1], pl, vh[1], vh[3]);
                mma_bf16(o[g * 2 + 1], ph, vl[1], vl[3]);
            }
        }
        __syncthreads();   // all warps done with stage t before it is refilled
    }

    // ---- normalize + write ctx split hi/lo ----
    const float inv0 = 1.0f / l_s[0];
    const float inv1 = 1.0f / l_s[1];
    #pragma unroll
    for (int f = 0; f < 8; f++) {
        const int col = h * 64 + f * 8 + (lane & 3) * 2;
        uint32_t h0, l0, h1, l1;
        split2(o[f][0] * inv0, o[f][1] * inv0, h0, l0);
        split2(o[f][2] * inv1, o[f][3] * inv1, h1, l1);
        *(uint32_t*)&g_ctxh[(size_t)row0 * DM + col] = h0;
        *(uint32_t*)&g_ctxl[(size_t)row0 * DM + col] = l0;
        *(uint32_t*)&g_ctxh[(size_t)row1 * DM + col] = h1;
        *(uint32_t*)&g_ctxl[(size_t)row1 * DM + col] = l1;
    }
}

// ---------------------------------------------------------------------------
extern "C" void kernel_launch(void* const* d_in, const int* in_sizes, int n_in,
                              void* d_out, int out_size)
{
    const float* x  = (const float*)d_in[0];
    const float* Wq = (const float*)d_in[1];
    const float* Wk = (const float*)d_in[2];
    const float* Wv = (const float*)d_in[3];
    const float* Wo = (const float*)d_in[4];
    float* out = (float*)d_out;

    __nv_bfloat16 *xh, *xl, *wqh, *wql, *wkh, *wkl, *wvh, *wvl, *woh, *wol;
    __nv_bfloat16 *qh, *ql, *kh, *kl, *vth, *vtl, *ch, *cl;
    cudaGetSymbolAddress((void**)&xh,  g_xh);   cudaGetSymbolAddress((void**)&xl,  g_xl);
    cudaGetSymbolAddress((void**)&wqh, g_Wqh);  cudaGetSymbolAddress((void**)&wql, g_Wql);
    cudaGetSymbolAddress((void**)&wkh, g_Wkh);  cudaGetSymbolAddress((void**)&wkl, g_Wkl);
    cudaGetSymbolAddress((void**)&wvh, g_Wvh);  cudaGetSymbolAddress((void**)&wvl, g_Wvl);
    cudaGetSymbolAddress((void**)&woh, g_Woh);  cudaGetSymbolAddress((void**)&wol, g_Wol);
    cudaGetSymbolAddress((void**)&qh,  g_Qh);   cudaGetSymbolAddress((void**)&ql,  g_Ql);
    cudaGetSymbolAddress((void**)&kh,  g_Kh);   cudaGetSymbolAddress((void**)&kl,  g_Kl);
    cudaGetSymbolAddress((void**)&vth, g_Vth);  cudaGetSymbolAddress((void**)&vtl, g_Vtl);
    cudaGetSymbolAddress((void**)&ch,  g_ctxh); cudaGetSymbolAddress((void**)&cl,  g_ctxl);

    cudaFuncSetAttribute(gemm_pre<0>,
                         cudaFuncAttributeMaxDynamicSharedMemorySize, GEMM_SMEM);
    cudaFuncSetAttribute(gemm_pre<1>,
                         cudaFuncAttributeMaxDynamicSharedMemorySize, GEMM_SMEM);
    cudaFuncSetAttribute(attn_tc,
                         cudaFuncAttributeMaxDynamicSharedMemorySize, ATTN_SMEM);

    const int nx4 = S_LEN * DM / 4;   // 786432
    const int nw4 = DM * DM / 4;      // 147456
    split_f32<<<(nx4 + 255) / 256, 256>>>(x,  xh,  xl,  nx4);
    split_f32<<<(nw4 + 255) / 256, 256>>>(Wq, wqh, wql, nw4);
    split_f32<<<(nw4 + 255) / 256, 256>>>(Wk, wkh, wkl, nw4);
    split_f32<<<(nw4 + 255) / 256, 256>>>(Wv, wvh, wvl, nw4);
    split_f32<<<(nw4 + 255) / 256, 256>>>(Wo, woh, wol, nw4);

    // Q[s][hd], K[s][hd]; V^T[hd][s] via swapped operands
    gemm_pre<1><<<dim3(S_LEN / 128, DM / 128), 256, GEMM_SMEM>>>(
        xh, xl, wqh, wql, nullptr, qh, ql, S_LEN, DM, DM);
    gemm_pre<1><<<dim3(S_LEN / 128, DM / 128), 256, GEMM_SMEM>>>(
        xh, xl, wkh, wkl, nullptr, kh, kl, S_LEN, DM, DM);
    gemm_pre<1><<<dim3(DM / 128, S_LEN / 128), 256, GEMM_SMEM>>>(
        wvh, wvl, xh, xl, nullptr, vth, vtl, DM, S_LEN, DM);

    attn_tc<<<dim3(S_LEN / 128, NH), 256, ATTN_SMEM>>>();

    gemm_pre<0><<<dim3(S_LEN / 128, DM / 128), 256, GEMM_SMEM>>>(
        ch, cl, woh, wol, out, nullptr, nullptr, S_LEN, DM, DM);
}

// round 6
// speedup vs baseline: 2.9168x; 1.1758x over previous
#include <cuda_runtime.h>
#include <cuda_bf16.h>
#include <cstdint>

#define S_LEN 4096
#define DM    768
#define NH    12
#define DK    64

// ---------------- scratch (device globals) ----------------
__device__ __nv_bfloat16 g_xh[S_LEN * DM],  g_xl[S_LEN * DM];
__device__ __nv_bfloat16 g_Wqh[DM * DM],    g_Wql[DM * DM];
__device__ __nv_bfloat16 g_Wkh[DM * DM],    g_Wkl[DM * DM];
__device__ __nv_bfloat16 g_Wvh[DM * DM],    g_Wvl[DM * DM];
__device__ __nv_bfloat16 g_Woh[DM * DM],    g_Wol[DM * DM];
__device__ __nv_bfloat16 g_Qh[S_LEN * DM],  g_Ql[S_LEN * DM];   // [s][hd]
__device__ __nv_bfloat16 g_Kh[S_LEN * DM],  g_Kl[S_LEN * DM];   // [s][hd]
__device__ __nv_bfloat16 g_Vth[DM * S_LEN], g_Vtl[DM * S_LEN];  // [hd][s]
__device__ __nv_bfloat16 g_ctxh[S_LEN * DM], g_ctxl[S_LEN * DM];

// ---------------- helpers ----------------
__device__ __forceinline__ uint32_t smem_u32(const void* p) {
    uint32_t a;
    asm("{ .reg .u64 t; cvta.to.shared.u64 t, %1; cvt.u32.u64 %0, t; }"
        : "=r"(a) : "l"(p));
    return a;
}
__device__ __forceinline__ void ldsm_x4(uint32_t* r, uint32_t addr) {
    asm volatile("ldmatrix.sync.aligned.m8n8.x4.shared.b16 {%0,%1,%2,%3}, [%4];"
                 : "=r"(r[0]), "=r"(r[1]), "=r"(r[2]), "=r"(r[3]) : "r"(addr));
}
__device__ __forceinline__ void mma_bf16(float* d, const uint32_t* a,
                                         uint32_t b0, uint32_t b1) {
    asm volatile("mma.sync.aligned.m16n8k16.row.col.f32.bf16.bf16.f32 "
                 "{%0,%1,%2,%3}, {%4,%5,%6,%7}, {%8,%9}, {%0,%1,%2,%3};"
                 : "+f"(d[0]), "+f"(d[1]), "+f"(d[2]), "+f"(d[3])
                 : "r"(a[0]), "r"(a[1]), "r"(a[2]), "r"(a[3]), "r"(b0), "r"(b1));
}
__device__ __forceinline__ void sts_v4(uint32_t addr, uint4 v) {
    asm volatile("st.shared.v4.b32 [%0], {%1, %2, %3, %4};"
                 :: "r"(addr), "r"(v.x), "r"(v.y), "r"(v.z), "r"(v.w) : "memory");
}
__device__ __forceinline__ void split2(float x, float y, uint32_t& hi, uint32_t& lo) {
    __nv_bfloat16 hx = __float2bfloat16(x), hy = __float2bfloat16(y);
    __nv_bfloat162 h2 = {hx, hy};
    hi = *(uint32_t*)&h2;
    __nv_bfloat162 l2 = {__float2bfloat16(x - __bfloat162float(hx)),
                         __float2bfloat16(y - __bfloat162float(hy))};
    lo = *(uint32_t*)&l2;
}
__device__ __forceinline__ void cp_async16(uint32_t dst, const void* src) {
    asm volatile("cp.async.cg.shared.global [%0], [%1], 16;"
                 :: "r"(dst), "l"(src));
}
#define CP_COMMIT() asm volatile("cp.async.commit_group;" ::: "memory")
#define CP_WAIT0()  asm volatile("cp.async.wait_group 0;" ::: "memory")

// ---------------- single fp32 -> bf16 hi/lo split pass for all 5 tensors ----
#define NX4 (S_LEN * DM / 4)
#define NW4 (DM * DM / 4)

__global__ __launch_bounds__(256)
void split_all(const float* __restrict__ x,  const float* __restrict__ Wq,
               const float* __restrict__ Wk, const float* __restrict__ Wv,
               const float* __restrict__ Wo)
{
    int i = blockIdx.x * blockDim.x + threadIdx.x;
    const float* in;
    __nv_bfloat16 *hi, *lo;
    int j = i;
    if (j < NX4)            { in = x;  hi = g_xh;  lo = g_xl;  }
    else if ((j -= NX4) < NW4)   { in = Wq; hi = g_Wqh; lo = g_Wql; }
    else if ((j -= NW4) < NW4)   { in = Wk; hi = g_Wkh; lo = g_Wkl; }
    else if ((j -= NW4) < NW4)   { in = Wv; hi = g_Wvh; lo = g_Wvl; }
    else if ((j -= NW4) < NW4)   { in = Wo; hi = g_Woh; lo = g_Wol; }
    else return;
    float4 v = ((const float4*)in)[j];
    uint32_t h0, l0, h1, l1;
    split2(v.x, v.y, h0, l0);
    split2(v.z, v.w, h1, l1);
    ((uint2*)hi)[j] = make_uint2(h0, h1);
    ((uint2*)lo)[j] = make_uint2(l0, l1);
}

// ===========================================================================
// bf16x3 GEMM body (pre-split inputs): C = A[M,K] @ B[N,K]^T
// ===========================================================================
#define ROWB      80
#define TILE_B    (128 * ROWB)
#define BUF_B     (4 * TILE_B)
#define GEMM_SMEM (2 * BUF_B)

template<int OMODE>
__device__ __forceinline__
void gemm_body(const __nv_bfloat16* __restrict__ Ah, const __nv_bfloat16* __restrict__ Al,
               const __nv_bfloat16* __restrict__ Bh, const __nv_bfloat16* __restrict__ Bl,
               float* __restrict__ C,
               __nv_bfloat16* __restrict__ Ch, __nv_bfloat16* __restrict__ Cl,
               int M, int N, int K, int bm, int bn, uint32_t sbase)
{
    const int tid  = threadIdx.x;
    const int lane = tid & 31;
    const int warp = tid >> 5;
    const int m0 = (warp >> 1) * 32;
    const int n0 = (warp & 1) * 64;

    float acc[2][8][4];
    #pragma unroll
    for (int mt = 0; mt < 2; mt++)
        #pragma unroll
        for (int nf = 0; nf < 8; nf++)
            #pragma unroll
            for (int e = 0; e < 4; e++) acc[mt][nf][e] = 0.0f;

    const int nchunk = K / 32;

    auto issue = [&](int c) {
        const uint32_t buf = sbase + (uint32_t)(c & 1) * BUF_B;
        const int kc = c * 32;
        #pragma unroll
        for (int j = 0; j < 8; j++) {
            const int idx = tid + j * 256;
            const int tile = idx >> 9;
            const int rem  = idx & 511;
            const int row  = rem >> 2;
            const int ch   = rem & 3;
            const uint32_t dst = buf + (uint32_t)tile * TILE_B + row * ROWB + ch * 16;
            const __nv_bfloat16* src;
            if (tile == 0)      src = &Ah[(size_t)(bm + row) * K + kc + ch * 8];
            else if (tile == 1) src = &Al[(size_t)(bm + row) * K + kc + ch * 8];
            else if (tile == 2) src = &Bh[(size_t)(bn + row) * K + kc + ch * 8];
            else                src = &Bl[(size_t)(bn + row) * K + kc + ch * 8];
            cp_async16(dst, src);
        }
        CP_COMMIT();
    };

    issue(0);

    const uint32_t lrow = (lane & 15);
    const uint32_t koff = (lane >> 4) * 16;

    for (int c = 0; c < nchunk; ++c) {
        CP_WAIT0();
        __syncthreads();
        if (c + 1 < nchunk) issue(c + 1);

        const uint32_t buf = sbase + (uint32_t)(c & 1) * BUF_B;
        #pragma unroll
        for (int ks = 0; ks < 2; ks++) {
            const uint32_t kb = ks * 32 + koff;
            uint32_t ah[2][4], al[2][4];
            #pragma unroll
            for (int mt = 0; mt < 2; mt++) {
                const uint32_t ro = (uint32_t)(m0 + mt * 16 + lrow) * ROWB + kb;
                ldsm_x4(ah[mt], buf + 0 * TILE_B + ro);
                ldsm_x4(al[mt], buf + 1 * TILE_B + ro);
            }
            uint32_t bh[4][4], bl[4][4];
            #pragma unroll
            for (int g = 0; g < 4; g++) {
                const uint32_t ro = (uint32_t)(n0 + g * 16 + lrow) * ROWB + kb;
                ldsm_x4(bh[g], buf + 2 * TILE_B + ro);
                ldsm_x4(bl[g], buf + 3 * TILE_B + ro);
            }
            #pragma unroll
            for (int mt = 0; mt < 2; mt++) {
                #pragma unroll
                for (int g = 0; g < 4; g++) {
                    mma_bf16(acc[mt][g * 2 + 0], ah[mt], bh[g][0], bh[g][2]);
                    mma_bf16(acc[mt][g * 2 + 0], ah[mt], bl[g][0], bl[g][2]);
                    mma_bf16(acc[mt][g * 2 + 0], al[mt], bh[g][0], bh[g][2]);
                    mma_bf16(acc[mt][g * 2 + 1], ah[mt], bh[g][1], bh[g][3]);
                    mma_bf16(acc[mt][g * 2 + 1], ah[mt], bl[g][1], bl[g][3]);
                    mma_bf16(acc[mt][g * 2 + 1], al[mt], bh[g][1], bh[g][3]);
                }
            }
        }
        __syncthreads();
    }

    #pragma unroll
    for (int mt = 0; mt < 2; mt++) {
        const int row = bm + m0 + mt * 16 + (lane >> 2);
        #pragma unroll
        for (int nf = 0; nf < 8; nf++) {
            const int col = bn + n0 + nf * 8 + (lane & 3) * 2;
            if (OMODE == 0) {
                *(float2*)&C[(size_t)row * N + col] =
                    make_float2(acc[mt][nf][0], acc[mt][nf][1]);
                *(float2*)&C[(size_t)(row + 8) * N + col] =
                    make_float2(acc[mt][nf][2], acc[mt][nf][3]);
            } else {
                uint32_t h0, l0, h1, l1;
                split2(acc[mt][nf][0], acc[mt][nf][1], h0, l0);
                split2(acc[mt][nf][2], acc[mt][nf][3], h1, l1);
                *(uint32_t*)&Ch[(size_t)row * N + col]       = h0;
                *(uint32_t*)&Cl[(size_t)row * N + col]       = l0;
                *(uint32_t*)&Ch[(size_t)(row + 8) * N + col] = h1;
                *(uint32_t*)&Cl[(size_t)(row + 8) * N + col] = l1;
            }
        }
    }
}

// Merged Q/K/V projection: grid (32, 6, 3); z selects operand set.
__global__ __launch_bounds__(256)
void gemm_qkv()
{
    extern __shared__ __align__(128) char dynsm[];
    const uint32_t sbase = smem_u32(dynsm);
    const int z = blockIdx.z;

    if (z == 0) {
        gemm_body<1>(g_xh, g_xl, g_Wqh, g_Wql, nullptr, g_Qh, g_Ql,
                     S_LEN, DM, DM, blockIdx.x * 128, blockIdx.y * 128, sbase);
    } else if (z == 1) {
        gemm_body<1>(g_xh, g_xl, g_Wkh, g_Wkl, nullptr, g_Kh, g_Kl,
                     S_LEN, DM, DM, blockIdx.x * 128, blockIdx.y * 128, sbase);
    } else {
        // V^T[hd][s] = Wv @ x^T : swap tile roles (bm over DM, bn over S_LEN)
        gemm_body<1>(g_Wvh, g_Wvl, g_xh, g_xl, nullptr, g_Vth, g_Vtl,
                     DM, S_LEN, DM, blockIdx.y * 128, blockIdx.x * 128, sbase);
    }
}

// Output projection: out = ctx @ Wo^T (fp32 out)
__global__ __launch_bounds__(256)
void gemm_out(float* __restrict__ out)
{
    extern __shared__ __align__(128) char dynsm[];
    const uint32_t sbase = smem_u32(dynsm);
    gemm_body<0>(g_ctxh, g_ctxl, g_Woh, g_Wol, out, nullptr, nullptr,
                 S_LEN, DM, DM, blockIdx.x * 128, blockIdx.y * 128, sbase);
}

// ===========================================================================
// Tensor-core causal flash attention (bf16x3), cp.async double-buffered K/V.
// ===========================================================================
#define AROWB 144
#define AQH   0
#define AQL   (128 * AROWB)
#define AKV   (2 * 128 * AROWB)
#define KVSTG 32768
#define KH_O  0
#define KL_O  8192
#define VH_O  16384
#define VL_O  24576
#define ATTN_SMEM (AKV + 2 * KVSTG)

__global__ __launch_bounds__(256, 2)
void attn_tc()
{
    extern __shared__ __align__(128) char dynbuf[];
    const uint32_t sb = smem_u32(dynbuf);

    const int tid  = threadIdx.x;
    const int lane = tid & 31;
    const int warp = tid >> 5;
    const int wr   = warp * 16;
    const int qb   = (int)gridDim.x - 1 - (int)blockIdx.x;
    const int h    = blockIdx.y;
    const int q0   = qb * 128;

    {
        const int gr = tid >> 3;
        const int gc = tid & 7;
        #pragma unroll
        for (int i = 0; i < 4; i++) {
            const int r = gr + i * 32;
            const uint32_t soff = (uint32_t)r * AROWB + gc * 16;
            uint4 vh = *(const uint4*)&g_Qh[(size_t)(q0 + r) * DM + h * 64 + gc * 8];
            uint4 vl = *(const uint4*)&g_Ql[(size_t)(q0 + r) * DM + h * 64 + gc * 8];
            sts_v4(sb + AQH + soff, vh);
            sts_v4(sb + AQL + soff, vl);
        }
    }

    auto issue_kv = [&](int t) {
        const uint32_t kvb = sb + AKV + (uint32_t)(t & 1) * KVSTG;
        const int k0 = t * 64;
        #pragma unroll
        for (int j = 0; j < 8; j++) {
            const int idx = tid + j * 256;
            const int arr = idx >> 9;
            const int rem = idx & 511;
            const int row = rem >> 3;
            const int c   = rem & 7;
            const uint32_t dst = kvb + (uint32_t)arr * 8192 + row * 128 +
                                 ((uint32_t)(c ^ (row & 7)) << 4);
            const __nv_bfloat16* src;
            if (arr == 0)      src = &g_Kh[(size_t)(k0 + row) * DM + h * 64 + c * 8];
            else if (arr == 1) src = &g_Kl[(size_t)(k0 + row) * DM + h * 64 + c * 8];
            else if (arr == 2) src = &g_Vth[(size_t)(h * 64 + row) * S_LEN + k0 + c * 8];
            else               src = &g_Vtl[(size_t)(h * 64 + row) * S_LEN + k0 + c * 8];
            cp_async16(dst, src);
        }
        CP_COMMIT();
    };

    issue_kv(0);

    float o[8][4];
    #pragma unroll
    for (int f = 0; f < 8; f++)
        #pragma unroll
        for (int e = 0; e < 4; e++) o[f][e] = 0.0f;
    float m_s[2] = {-1e30f, -1e30f};
    float l_s[2] = {0.0f, 0.0f};

    const int row0 = q0 + wr + (lane >> 2);
    const int row1 = row0 + 8;
    const uint32_t lrow = (lane & 15);
    const uint32_t koff = (lane >> 4) * 16;
    const int ntile = 2 * qb + 2;

    for (int t = 0; t < ntile; ++t) {
        const int k0 = t * 64;
        CP_WAIT0();
        __syncthreads();
        if (t + 1 < ntile) issue_kv(t + 1);

        const uint32_t kvb = sb + AKV + (uint32_t)(t & 1) * KVSTG;

        float sacc[8][4];
        #pragma unroll
        for (int f = 0; f < 8; f++)
            #pragma unroll
            for (int e = 0; e < 4; e++) sacc[f][e] = 0.0f;

        #pragma unroll
        for (int ks = 0; ks < 4; ks++) {
            uint32_t qh[4], ql[4];
            const uint32_t qoff = (uint32_t)(wr + lrow) * AROWB + ks * 32 + koff;
            ldsm_x4(qh, sb + AQH + qoff);
            ldsm_x4(ql, sb + AQL + qoff);
            const uint32_t cidx = ks * 2 + (lane >> 4);
            #pragma unroll
            for (int g = 0; g < 4; g++) {
                const uint32_t row = g * 16 + lrow;
                const uint32_t ro = row * 128 + ((cidx ^ (row & 7)) << 4);
                uint32_t kh[4], kl[4];
                ldsm_x4(kh, kvb + KH_O + ro);
                ldsm_x4(kl, kvb + KL_O + ro);
                mma_bf16(sacc[g * 2 + 0], qh, kh[0], kh[2]);
                mma_bf16(sacc[g * 2 + 0], qh, kl[0], kl[2]);
                mma_bf16(sacc[g * 2 + 0], ql, kh[0], kh[2]);
                mma_bf16(sacc[g * 2 + 1], qh, kh[1], kh[3]);
                mma_bf16(sacc[g * 2 + 1], qh, kl[1], kl[3]);
                mma_bf16(sacc[g * 2 + 1], ql, kh[1], kh[3]);
            }
        }

        const float scale = 0.125f;
        if (t >= 2 * qb) {
            #pragma unroll
            for (int f = 0; f < 8; f++) {
                const int cb = k0 + f * 8 + (lane & 3) * 2;
                sacc[f][0] = (cb     > row0) ? -1e30f : sacc[f][0] * scale;
                sacc[f][1] = (cb + 1 > row0) ? -1e30f : sacc[f][1] * scale;
                sacc[f][2] = (cb     > row1) ? -1e30f : sacc[f][2] * scale;
                sacc[f][3] = (cb + 1 > row1) ? -1e30f : sacc[f][3] * scale;
            }
        } else {
            #pragma unroll
            for (int f = 0; f < 8; f++)
                #pragma unroll
                for (int e = 0; e < 4; e++) sacc[f][e] *= scale;
        }

        float rm0 = -1e30f, rm1 = -1e30f;
        #pragma unroll
        for (int f = 0; f < 8; f++) {
            rm0 = fmaxf(rm0, fmaxf(sacc[f][0], sacc[f][1]));
            rm1 = fmaxf(rm1, fmaxf(sacc[f][2], sacc[f][3]));
        }
        #pragma unroll
        for (int off = 1; off < 4; off <<= 1) {
            rm0 = fmaxf(rm0, __shfl_xor_sync(0xffffffffu, rm0, off));
            rm1 = fmaxf(rm1, __shfl_xor_sync(0xffffffffu, rm1, off));
        }
        const float mn0 = fmaxf(m_s[0], rm0);
        const float mn1 = fmaxf(m_s[1], rm1);
        const float al0 = __expf(m_s[0] - mn0);
        const float al1 = __expf(m_s[1] - mn1);
        float rs0 = 0.0f, rs1 = 0.0f;
        #pragma unroll
        for (int f = 0; f < 8; f++) {
            sacc[f][0] = __expf(sacc[f][0] - mn0);
            sacc[f][1] = __expf(sacc[f][1] - mn0);
            sacc[f][2] = __expf(sacc[f][2] - mn1);
            sacc[f][3] = __expf(sacc[f][3] - mn1);
            rs0 += sacc[f][0] + sacc[f][1];
            rs1 += sacc[f][2] + sacc[f][3];
        }
        #pragma unroll
        for (int off = 1; off < 4; off <<= 1) {
            rs0 += __shfl_xor_sync(0xffffffffu, rs0, off);
            rs1 += __shfl_xor_sync(0xffffffffu, rs1, off);
        }
        l_s[0] = l_s[0] * al0 + rs0;
        l_s[1] = l_s[1] * al1 + rs1;
        m_s[0] = mn0;
        m_s[1] = mn1;
        #pragma unroll
        for (int f = 0; f < 8; f++) {
            o[f][0] *= al0; o[f][1] *= al0;
            o[f][2] *= al1; o[f][3] *= al1;
        }

        #pragma unroll
        for (int ks = 0; ks < 4; ks++) {
            const float* s0 = sacc[2 * ks];
            const float* s1 = sacc[2 * ks + 1];
            uint32_t ph[4], pl[4];
            split2(s0[0], s0[1], ph[0], pl[0]);
            split2(s0[2], s0[3], ph[1], pl[1]);
            split2(s1[0], s1[1], ph[2], pl[2]);
            split2(s1[2], s1[3], ph[3], pl[3]);
            const uint32_t cidx = ks * 2 + (lane >> 4);
            #pragma unroll
            for (int g = 0; g < 4; g++) {
                const uint32_t row = g * 16 + lrow;
                const uint32_t ro = row * 128 + ((cidx ^ (row & 7)) << 4);
                uint32_t vh[4], vl[4];
                ldsm_x4(vh, kvb + VH_O + ro);
                ldsm_x4(vl, kvb + VL_O + ro);
                mma_bf16(o[g * 2 + 0], ph, vh[0], vh[2]);
                mma_bf16(o[g * 2 + 0], pl, vh[0], vh[2]);
                mma_bf16(o[g * 2 + 0], ph, vl[0], vl[2]);
                mma_bf16(o[g * 2 + 1], ph, vh[1], vh[3]);
                mma_bf16(o[g * 2 + 1], pl, vh[1], vh[3]);
                mma_bf16(o[g * 2 + 1], ph, vl[1], vl[3]);
            }
        }
        __syncthreads();
    }

    const float inv0 = 1.0f / l_s[0];
    const float inv1 = 1.0f / l_s[1];
    #pragma unroll
    for (int f = 0; f < 8; f++) {
        const int col = h * 64 + f * 8 + (lane & 3) * 2;
        uint32_t h0, l0, h1, l1;
        split2(o[f][0] * inv0, o[f][1] * inv0, h0, l0);
        split2(o[f][2] * inv1, o[f][3] * inv1, h1, l1);
        *(uint32_t*)&g_ctxh[(size_t)row0 * DM + col] = h0;
        *(uint32_t*)&g_ctxl[(size_t)row0 * DM + col] = l0;
        *(uint32_t*)&g_ctxh[(size_t)row1 * DM + col] = h1;
        *(uint32_t*)&g_ctxl[(size_t)row1 * DM + col] = l1;
    }
}

// ---------------------------------------------------------------------------
extern "C" void kernel_launch(void* const* d_in, const int* in_sizes, int n_in,
                              void* d_out, int out_size)
{
    const float* x  = (const float*)d_in[0];
    const float* Wq = (const float*)d_in[1];
    const float* Wk = (const float*)d_in[2];
    const float* Wv = (const float*)d_in[3];
    const float* Wo = (const float*)d_in[4];
    float* out = (float*)d_out;

    cudaFuncSetAttribute(gemm_qkv,
                         cudaFuncAttributeMaxDynamicSharedMemorySize, GEMM_SMEM);
    cudaFuncSetAttribute(gemm_out,
                         cudaFuncAttributeMaxDynamicSharedMemorySize, GEMM_SMEM);
    cudaFuncSetAttribute(attn_tc,
                         cudaFuncAttributeMaxDynamicSharedMemorySize, ATTN_SMEM);

    const int ntot4 = NX4 + 4 * NW4;
    split_all<<<(ntot4 + 255) / 256, 256>>>(x, Wq, Wk, Wv, Wo);

    gemm_qkv<<<dim3(S_LEN / 128, DM / 128, 3), 256, GEMM_SMEM>>>();

    attn_tc<<<dim3(S_LEN / 128, NH), 256, ATTN_SMEM>>>();

    gemm_out<<<dim3(S_LEN / 128, DM / 128), 256, GEMM_SMEM>>>(out);
}

// round 7
// speedup vs baseline: 2.9224x; 1.0019x over previous
#include <cuda_runtime.h>
#include <cuda_bf16.h>
#include <cstdint>

#define S_LEN 4096
#define DM    768
#define NH    12
#define DK    64

// ---------------- scratch (device globals) ----------------
__device__ __nv_bfloat16 g_xh[S_LEN * DM],  g_xl[S_LEN * DM];
__device__ __nv_bfloat16 g_Wqh[DM * DM],    g_Wql[DM * DM];
__device__ __nv_bfloat16 g_Wkh[DM * DM],    g_Wkl[DM * DM];
__device__ __nv_bfloat16 g_Wvh[DM * DM],    g_Wvl[DM * DM];
__device__ __nv_bfloat16 g_Woh[DM * DM],    g_Wol[DM * DM];
__device__ __nv_bfloat16 g_Qh[S_LEN * DM],  g_Ql[S_LEN * DM];   // [s][hd]
__device__ __nv_bfloat16 g_Kh[S_LEN * DM],  g_Kl[S_LEN * DM];   // [s][hd]
__device__ __nv_bfloat16 g_Vth[DM * S_LEN], g_Vtl[DM * S_LEN];  // [hd][s]
__device__ __nv_bfloat16 g_ctxh[S_LEN * DM], g_ctxl[S_LEN * DM];

// ---------------- helpers ----------------
__device__ __forceinline__ uint32_t smem_u32(const void* p) {
    uint32_t a;
    asm("{ .reg .u64 t; cvta.to.shared.u64 t, %1; cvt.u32.u64 %0, t; }"
        : "=r"(a) : "l"(p));
    return a;
}
__device__ __forceinline__ void ldsm_x4(uint32_t* r, uint32_t addr) {
    asm volatile("ldmatrix.sync.aligned.m8n8.x4.shared.b16 {%0,%1,%2,%3}, [%4];"
                 : "=r"(r[0]), "=r"(r[1]), "=r"(r[2]), "=r"(r[3]) : "r"(addr));
}
__device__ __forceinline__ void mma_bf16(float* d, const uint32_t* a,
                                         uint32_t b0, uint32_t b1) {
    asm volatile("mma.sync.aligned.m16n8k16.row.col.f32.bf16.bf16.f32 "
                 "{%0,%1,%2,%3}, {%4,%5,%6,%7}, {%8,%9}, {%0,%1,%2,%3};"
                 : "+f"(d[0]), "+f"(d[1]), "+f"(d[2]), "+f"(d[3])
                 : "r"(a[0]), "r"(a[1]), "r"(a[2]), "r"(a[3]), "r"(b0), "r"(b1));
}
__device__ __forceinline__ void sts_v4(uint32_t addr, uint4 v) {
    asm volatile("st.shared.v4.b32 [%0], {%1, %2, %3, %4};"
                 :: "r"(addr), "r"(v.x), "r"(v.y), "r"(v.z), "r"(v.w) : "memory");
}
__device__ __forceinline__ void split2(float x, float y, uint32_t& hi, uint32_t& lo) {
    __nv_bfloat16 hx = __float2bfloat16(x), hy = __float2bfloat16(y);
    __nv_bfloat162 h2 = {hx, hy};
    hi = *(uint32_t*)&h2;
    __nv_bfloat162 l2 = {__float2bfloat16(x - __bfloat162float(hx)),
                         __float2bfloat16(y - __bfloat162float(hy))};
    lo = *(uint32_t*)&l2;
}
__device__ __forceinline__ void cp_async16(uint32_t dst, const void* src) {
    asm volatile("cp.async.cg.shared.global [%0], [%1], 16;"
                 :: "r"(dst), "l"(src));
}
#define CP_COMMIT() asm volatile("cp.async.commit_group;" ::: "memory")
#define CP_WAIT0()  asm volatile("cp.async.wait_group 0;" ::: "memory")

// ---------------- single fp32 -> bf16 hi/lo split pass for all 5 tensors ----
#define NX4 (S_LEN * DM / 4)
#define NW4 (DM * DM / 4)

__global__ __launch_bounds__(256)
void split_all(const float* __restrict__ x,  const float* __restrict__ Wq,
               const float* __restrict__ Wk, const float* __restrict__ Wv,
               const float* __restrict__ Wo)
{
    int i = blockIdx.x * blockDim.x + threadIdx.x;
    const float* in;
    __nv_bfloat16 *hi, *lo;
    int j = i;
    if (j < NX4)            { in = x;  hi = g_xh;  lo = g_xl;  }
    else if ((j -= NX4) < NW4)   { in = Wq; hi = g_Wqh; lo = g_Wql; }
    else if ((j -= NW4) < NW4)   { in = Wk; hi = g_Wkh; lo = g_Wkl; }
    else if ((j -= NW4) < NW4)   { in = Wv; hi = g_Wvh; lo = g_Wvl; }
    else if ((j -= NW4) < NW4)   { in = Wo; hi = g_Woh; lo = g_Wol; }
    else return;
    float4 v = ((const float4*)in)[j];
    uint32_t h0, l0, h1, l1;
    split2(v.x, v.y, h0, l0);
    split2(v.z, v.w, h1, l1);
    ((uint2*)hi)[j] = make_uint2(h0, h1);
    ((uint2*)lo)[j] = make_uint2(l0, l1);
}

// ===========================================================================
// bf16x3 GEMM body (pre-split inputs): C = A[M,K] @ B[N,K]^T
// ===========================================================================
#define ROWB      80
#define TILE_B    (128 * ROWB)
#define BUF_B     (4 * TILE_B)
#define GEMM_SMEM (2 * BUF_B)

template<int OMODE>
__device__ __forceinline__
void gemm_body(const __nv_bfloat16* __restrict__ Ah, const __nv_bfloat16* __restrict__ Al,
               const __nv_bfloat16* __restrict__ Bh, const __nv_bfloat16* __restrict__ Bl,
               float* __restrict__ C,
               __nv_bfloat16* __restrict__ Ch, __nv_bfloat16* __restrict__ Cl,
               int M, int N, int K, int bm, int bn, uint32_t sbase)
{
    const int tid  = threadIdx.x;
    const int lane = tid & 31;
    const int warp = tid >> 5;
    const int m0 = (warp >> 1) * 32;
    const int n0 = (warp & 1) * 64;

    float acc[2][8][4];
    #pragma unroll
    for (int mt = 0; mt < 2; mt++)
        #pragma unroll
        for (int nf = 0; nf < 8; nf++)
            #pragma unroll
            for (int e = 0; e < 4; e++) acc[mt][nf][e] = 0.0f;

    const int nchunk = K / 32;

    auto issue = [&](int c) {
        const uint32_t buf = sbase + (uint32_t)(c & 1) * BUF_B;
        const int kc = c * 32;
        #pragma unroll
        for (int j = 0; j < 8; j++) {
            const int idx = tid + j * 256;
            const int tile = idx >> 9;
            const int rem  = idx & 511;
            const int row  = rem >> 2;
            const int ch   = rem & 3;
            const uint32_t dst = buf + (uint32_t)tile * TILE_B + row * ROWB + ch * 16;
            const __nv_bfloat16* src;
            if (tile == 0)      src = &Ah[(size_t)(bm + row) * K + kc + ch * 8];
            else if (tile == 1) src = &Al[(size_t)(bm + row) * K + kc + ch * 8];
            else if (tile == 2) src = &Bh[(size_t)(bn + row) * K + kc + ch * 8];
            else                src = &Bl[(size_t)(bn + row) * K + kc + ch * 8];
            cp_async16(dst, src);
        }
        CP_COMMIT();
    };

    issue(0);

    const uint32_t lrow = (lane & 15);
    const uint32_t koff = (lane >> 4) * 16;

    for (int c = 0; c < nchunk; ++c) {
        CP_WAIT0();
        __syncthreads();
        if (c + 1 < nchunk) issue(c + 1);

        const uint32_t buf = sbase + (uint32_t)(c & 1) * BUF_B;
        #pragma unroll
        for (int ks = 0; ks < 2; ks++) {
            const uint32_t kb = ks * 32 + koff;
            uint32_t ah[2][4], al[2][4];
            #pragma unroll
            for (int mt = 0; mt < 2; mt++) {
                const uint32_t ro = (uint32_t)(m0 + mt * 16 + lrow) * ROWB + kb;
                ldsm_x4(ah[mt], buf + 0 * TILE_B + ro);
                ldsm_x4(al[mt], buf + 1 * TILE_B + ro);
            }
            uint32_t bh[4][4], bl[4][4];
            #pragma unroll
            for (int g = 0; g < 4; g++) {
                const uint32_t ro = (uint32_t)(n0 + g * 16 + lrow) * ROWB + kb;
                ldsm_x4(bh[g], buf + 2 * TILE_B + ro);
                ldsm_x4(bl[g], buf + 3 * TILE_B + ro);
            }
            #pragma unroll
            for (int mt = 0; mt < 2; mt++) {
                #pragma unroll
                for (int g = 0; g < 4; g++) {
                    mma_bf16(acc[mt][g * 2 + 0], ah[mt], bh[g][0], bh[g][2]);
                    mma_bf16(acc[mt][g * 2 + 0], ah[mt], bl[g][0], bl[g][2]);
                    mma_bf16(acc[mt][g * 2 + 0], al[mt], bh[g][0], bh[g][2]);
                    mma_bf16(acc[mt][g * 2 + 1], ah[mt], bh[g][1], bh[g][3]);
                    mma_bf16(acc[mt][g * 2 + 1], ah[mt], bl[g][1], bl[g][3]);
                    mma_bf16(acc[mt][g * 2 + 1], al[mt], bh[g][1], bh[g][3]);
                }
            }
        }
        __syncthreads();
    }

    #pragma unroll
    for (int mt = 0; mt < 2; mt++) {
        const int row = bm + m0 + mt * 16 + (lane >> 2);
        #pragma unroll
        for (int nf = 0; nf < 8; nf++) {
            const int col = bn + n0 + nf * 8 + (lane & 3) * 2;
            if (OMODE == 0) {
                *(float2*)&C[(size_t)row * N + col] =
                    make_float2(acc[mt][nf][0], acc[mt][nf][1]);
                *(float2*)&C[(size_t)(row + 8) * N + col] =
                    make_float2(acc[mt][nf][2], acc[mt][nf][3]);
            } else {
                uint32_t h0, l0, h1, l1;
                split2(acc[mt][nf][0], acc[mt][nf][1], h0, l0);
                split2(acc[mt][nf][2], acc[mt][nf][3], h1, l1);
                *(uint32_t*)&Ch[(size_t)row * N + col]       = h0;
                *(uint32_t*)&Cl[(size_t)row * N + col]       = l0;
                *(uint32_t*)&Ch[(size_t)(row + 8) * N + col] = h1;
                *(uint32_t*)&Cl[(size_t)(row + 8) * N + col] = l1;
            }
        }
    }
}

// Merged Q/K/V projection: grid (32, 6, 3); z selects operand set.
__global__ __launch_bounds__(256, 2)
void gemm_qkv()
{
    extern __shared__ __align__(128) char dynsm[];
    const uint32_t sbase = smem_u32(dynsm);
    const int z = blockIdx.z;

    if (z == 0) {
        gemm_body<1>(g_xh, g_xl, g_Wqh, g_Wql, nullptr, g_Qh, g_Ql,
                     S_LEN, DM, DM, blockIdx.x * 128, blockIdx.y * 128, sbase);
    } else if (z == 1) {
        gemm_body<1>(g_xh, g_xl, g_Wkh, g_Wkl, nullptr, g_Kh, g_Kl,
                     S_LEN, DM, DM, blockIdx.x * 128, blockIdx.y * 128, sbase);
    } else {
        // V^T[hd][s] = Wv @ x^T : swap tile roles (bm over DM, bn over S_LEN)
        gemm_body<1>(g_Wvh, g_Wvl, g_xh, g_xl, nullptr, g_Vth, g_Vtl,
                     DM, S_LEN, DM, blockIdx.y * 128, blockIdx.x * 128, sbase);
    }
}

// Output projection: out = ctx @ Wo^T (fp32 out)
__global__ __launch_bounds__(256, 2)
void gemm_out(float* __restrict__ out)
{
    extern __shared__ __align__(128) char dynsm[];
    const uint32_t sbase = smem_u32(dynsm);
    gemm_body<0>(g_ctxh, g_ctxl, g_Woh, g_Wol, out, nullptr, nullptr,
                 S_LEN, DM, DM, blockIdx.x * 128, blockIdx.y * 128, sbase);
}

// ===========================================================================
// Tensor-core causal flash attention (bf16x3), cp.async double-buffered K/V.
// ===========================================================================
#define AROWB 144
#define AQH   0
#define AQL   (128 * AROWB)
#define AKV   (2 * 128 * AROWB)
#define KVSTG 32768
#define KH_O  0
#define KL_O  8192
#define VH_O  16384
#define VL_O  24576
#define ATTN_SMEM (AKV + 2 * KVSTG)

__global__ __launch_bounds__(256, 2)
void attn_tc()
{
    extern __shared__ __align__(128) char dynbuf[];
    const uint32_t sb = smem_u32(dynbuf);

    const int tid  = threadIdx.x;
    const int lane = tid & 31;
    const int warp = tid >> 5;
    const int wr   = warp * 16;
    const int qb   = (int)gridDim.x - 1 - (int)blockIdx.x;
    const int h    = blockIdx.y;
    const int q0   = qb * 128;

    {
        const int gr = tid >> 3;
        const int gc = tid & 7;
        #pragma unroll
        for (int i = 0; i < 4; i++) {
            const int r = gr + i * 32;
            const uint32_t soff = (uint32_t)r * AROWB + gc * 16;
            uint4 vh = *(const uint4*)&g_Qh[(size_t)(q0 + r) * DM + h * 64 + gc * 8];
            uint4 vl = *(const uint4*)&g_Ql[(size_t)(q0 + r) * DM + h * 64 + gc * 8];
            sts_v4(sb + AQH + soff, vh);
            sts_v4(sb + AQL + soff, vl);
        }
    }

    auto issue_kv = [&](int t) {
        const uint32_t kvb = sb + AKV + (uint32_t)(t & 1) * KVSTG;
        const int k0 = t * 64;
        #pragma unroll
        for (int j = 0; j < 8; j++) {
            const int idx = tid + j * 256;
            const int arr = idx >> 9;
            const int rem = idx & 511;
            const int row = rem >> 3;
            const int c   = rem & 7;
            const uint32_t dst = kvb + (uint32_t)arr * 8192 + row * 128 +
                                 ((uint32_t)(c ^ (row & 7)) << 4);
            const __nv_bfloat16* src;
            if (arr == 0)      src = &g_Kh[(size_t)(k0 + row) * DM + h * 64 + c * 8];
            else if (arr == 1) src = &g_Kl[(size_t)(k0 + row) * DM + h * 64 + c * 8];
            else if (arr == 2) src = &g_Vth[(size_t)(h * 64 + row) * S_LEN + k0 + c * 8];
            else               src = &g_Vtl[(size_t)(h * 64 + row) * S_LEN + k0 + c * 8];
            cp_async16(dst, src);
        }
        CP_COMMIT();
    };

    issue_kv(0);

    float o[8][4];
    #pragma unroll
    for (int f = 0; f < 8; f++)
        #pragma unroll
        for (int e = 0; e < 4; e++) o[f][e] = 0.0f;
    float m_s[2] = {-1e30f, -1e30f};
    float l_s[2] = {0.0f, 0.0f};

    const int row0 = q0 + wr + (lane >> 2);
    const int row1 = row0 + 8;
    const uint32_t lrow = (lane & 15);
    const uint32_t koff = (lane >> 4) * 16;
    const int ntile = 2 * qb + 2;

    for (int t = 0; t < ntile; ++t) {
        const int k0 = t * 64;
        CP_WAIT0();
        __syncthreads();
        if (t + 1 < ntile) issue_kv(t + 1);

        const uint32_t kvb = sb + AKV + (uint32_t)(t & 1) * KVSTG;

        float sacc[8][4];
        #pragma unroll
        for (int f = 0; f < 8; f++)
            #pragma unroll
            for (int e = 0; e < 4; e++) sacc[f][e] = 0.0f;

        #pragma unroll
        for (int ks = 0; ks < 4; ks++) {
            uint32_t qh[4], ql[4];
            const uint32_t qoff = (uint32_t)(wr + lrow) * AROWB + ks * 32 + koff;
            ldsm_x4(qh, sb + AQH + qoff);
            ldsm_x4(ql, sb + AQL + qoff);
            const uint32_t cidx = ks * 2 + (lane >> 4);
            #pragma unroll
            for (int g = 0; g < 4; g++) {
                const uint32_t row = g * 16 + lrow;
                const uint32_t ro = row * 128 + ((cidx ^ (row & 7)) << 4);
                uint32_t kh[4], kl[4];
                ldsm_x4(kh, kvb + KH_O + ro);
                ldsm_x4(kl, kvb + KL_O + ro);
                mma_bf16(sacc[g * 2 + 0], qh, kh[0], kh[2]);
                mma_bf16(sacc[g * 2 + 0], qh, kl[0], kl[2]);
                mma_bf16(sacc[g * 2 + 0], ql, kh[0], kh[2]);
                mma_bf16(sacc[g * 2 + 1], qh, kh[1], kh[3]);
                mma_bf16(sacc[g * 2 + 1], qh, kl[1], kl[3]);
                mma_bf16(sacc[g * 2 + 1], ql, kh[1], kh[3]);
            }
        }

        const float scale = 0.125f;
        if (t >= 2 * qb) {
            #pragma unroll
            for (int f = 0; f < 8; f++) {
                const int cb = k0 + f * 8 + (lane & 3) * 2;
                sacc[f][0] = (cb     > row0) ? -1e30f : sacc[f][0] * scale;
                sacc[f][1] = (cb + 1 > row0) ? -1e30f : sacc[f][1] * scale;
                sacc[f][2] = (cb     > row1) ? -1e30f : sacc[f][2] * scale;
                sacc[f][3] = (cb + 1 > row1) ? -1e30f : sacc[f][3] * scale;
            }
        } else {
            #pragma unroll
            for (int f = 0; f < 8; f++)
                #pragma unroll
                for (int e = 0; e < 4; e++) sacc[f][e] *= scale;
        }

        float rm0 = -1e30f, rm1 = -1e30f;
        #pragma unroll
        for (int f = 0; f < 8; f++) {
            rm0 = fmaxf(rm0, fmaxf(sacc[f][0], sacc[f][1]));
            rm1 = fmaxf(rm1, fmaxf(sacc[f][2], sacc[f][3]));
        }
        #pragma unroll
        for (int off = 1; off < 4; off <<= 1) {
            rm0 = fmaxf(rm0, __shfl_xor_sync(0xffffffffu, rm0, off));
            rm1 = fmaxf(rm1, __shfl_xor_sync(0xffffffffu, rm1, off));
        }
        const float mn0 = fmaxf(m_s[0], rm0);
        const float mn1 = fmaxf(m_s[1], rm1);
        const float al0 = __expf(m_s[0] - mn0);
        const float al1 = __expf(m_s[1] - mn1);
        float rs0 = 0.0f, rs1 = 0.0f;
        #pragma unroll
        for (int f = 0; f < 8; f++) {
            sacc[f][0] = __expf(sacc[f][0] - mn0);
            sacc[f][1] = __expf(sacc[f][1] - mn0);
            sacc[f][2] = __expf(sacc[f][2] - mn1);
            sacc[f][3] = __expf(sacc[f][3] - mn1);
            rs0 += sacc[f][0] + sacc[f][1];
            rs1 += sacc[f][2] + sacc[f][3];
        }
        #pragma unroll
        for (int off = 1; off < 4; off <<= 1) {
            rs0 += __shfl_xor_sync(0xffffffffu, rs0, off);
            rs1 += __shfl_xor_sync(0xffffffffu, rs1, off);
        }
        l_s[0] = l_s[0] * al0 + rs0;
        l_s[1] = l_s[1] * al1 + rs1;
        m_s[0] = mn0;
        m_s[1] = mn1;
        #pragma unroll
        for (int f = 0; f < 8; f++) {
            o[f][0] *= al0; o[f][1] *= al0;
            o[f][2] *= al1; o[f][3] *= al1;
        }

        #pragma unroll
        for (int ks = 0; ks < 4; ks++) {
            const float* s0 = sacc[2 * ks];
            const float* s1 = sacc[2 * ks + 1];
            uint32_t ph[4], pl[4];
            split2(s0[0], s0[1], ph[0], pl[0]);
            split2(s0[2], s0[3], ph[1], pl[1]);
            split2(s1[0], s1[1], ph[2], pl[2]);
            split2(s1[2], s1[3], ph[3], pl[3]);
            const uint32_t cidx = ks * 2 + (lane >> 4);
            #pragma unroll
            for (int g = 0; g < 4; g++) {
                const uint32_t row = g * 16 + lrow;
                const uint32_t ro = row * 128 + ((cidx ^ (row & 7)) << 4);
                uint32_t vh[4], vl[4];
                ldsm_x4(vh, kvb + VH_O + ro);
                ldsm_x4(vl, kvb + VL_O + ro);
                mma_bf16(o[g * 2 + 0], ph, vh[0], vh[2]);
                mma_bf16(o[g * 2 + 0], pl, vh[0], vh[2]);
                mma_bf16(o[g * 2 + 0], ph, vl[0], vl[2]);
                mma_bf16(o[g * 2 + 1], ph, vh[1], vh[3]);
                mma_bf16(o[g * 2 + 1], pl, vh[1], vh[3]);
                mma_bf16(o[g * 2 + 1], ph, vl[1], vl[3]);
            }
        }
        __syncthreads();
    }

    const float inv0 = 1.0f / l_s[0];
    const float inv1 = 1.0f / l_s[1];
    #pragma unroll
    for (int f = 0; f < 8; f++) {
        const int col = h * 64 + f * 8 + (lane & 3) * 2;
        uint32_t h0, l0, h1, l1;
        split2(o[f][0] * inv0, o[f][1] * inv0, h0, l0);
        split2(o[f][2] * inv1, o[f][3] * inv1, h1, l1);
        *(uint32_t*)&g_ctxh[(size_t)row0 * DM + col] = h0;
        *(uint32_t*)&g_ctxl[(size_t)row0 * DM + col] = l0;
        *(uint32_t*)&g_ctxh[(size_t)row1 * DM + col] = h1;
        *(uint32_t*)&g_ctxl[(size_t)row1 * DM + col] = l1;
    }
}

// ---------------------------------------------------------------------------
extern "C" void kernel_launch(void* const* d_in, const int* in_sizes, int n_in,
                              void* d_out, int out_size)
{
    const float* x  = (const float*)d_in[0];
    const float* Wq = (const float*)d_in[1];
    const float* Wk = (const float*)d_in[2];
    const float* Wv = (const float*)d_in[3];
    const float* Wo = (const float*)d_in[4];
    float* out = (float*)d_out;

    cudaFuncSetAttribute(gemm_qkv,
                         cudaFuncAttributeMaxDynamicSharedMemorySize, GEMM_SMEM);
    cudaFuncSetAttribute(gemm_out,
                         cudaFuncAttributeMaxDynamicSharedMemorySize, GEMM_SMEM);
    cudaFuncSetAttribute(attn_tc,
                         cudaFuncAttributeMaxDynamicSharedMemorySize, ATTN_SMEM);

    const int ntot4 = NX4 + 4 * NW4;
    split_all<<<(ntot4 + 255) / 256, 256>>>(x, Wq, Wk, Wv, Wo);

    gemm_qkv<<<dim3(S_LEN / 128, DM / 128, 3), 256, GEMM_SMEM>>>();

    attn_tc<<<dim3(S_LEN / 128, NH), 256, ATTN_SMEM>>>();

    gemm_out<<<dim3(S_LEN / 128, DM / 128), 256, GEMM_SMEM>>>(out);
}